// round 1
// baseline (speedup 1.0000x reference)
#include <cuda_runtime.h>
#include <cuda_bf16.h>
#include <math.h>

// ---------------- problem constants ----------------
#define NN     16384          // nodes in batch subgraph
#define BB     4096           // events
#define EE     131072         // edges
#define MEMD   256            // memory dim
#define TDD    128            // time dim
#define MSGD   172            // raw msg dim
#define OCD    128            // per-head out channels
#define EDGED  300            // MSG + TD
#define GRUIN  812            // 2*MEM + MSG + TD
#define G3     768            // 3*MEM

// ---------------- device scratch (static; no allocs allowed) ----------------
__device__ float g_aggr[(size_t)NN * GRUIN];
__device__ float g_h   [(size_t)NN * MEMD];
__device__ float g_lu  [NN];
__device__ float g_gi  [(size_t)NN * G3];
__device__ float g_gh  [(size_t)NN * G3];
__device__ float g_mem [(size_t)NN * MEMD];
__device__ float g_qn  [(size_t)NN * MEMD];
__device__ float g_kn  [(size_t)NN * MEMD];
__device__ float g_vn  [(size_t)NN * MEMD];
__device__ float g_z   [(size_t)NN * MEMD];
__device__ float g_ea  [(size_t)EE * EDGED];
__device__ float g_eproj[(size_t)EE * MEMD];
__device__ float g_expa[(size_t)EE * 2];
__device__ float g_denom[(size_t)NN * 2];
__device__ float g_agg [(size_t)NN * MEMD];
__device__ float g_cat [(size_t)2 * BB * 512];
__device__ float g_hid [(size_t)2 * BB * 256];

// ---------------- generic fp32 GEMM: C[m,n] = A[m,:] . W[n,:] + bias[n] ----------------
// A: [M,K] row-major, W: [Nout,K] row-major (i.e. computes A @ W^T). M,Nout multiples of 64.
#define BM 64
#define BN 64
#define BK 16

__global__ __launch_bounds__(256) void gemm_tn(
    const float* __restrict__ A, const float* __restrict__ W,
    const float* __restrict__ bias, float* __restrict__ C,
    int Mrows, int Nout, int K, int do_relu)
{
    __shared__ float As[BK][BM + 4];
    __shared__ float Ws[BK][BN + 4];

    const int t  = threadIdx.x;
    const int tx = t & 15;
    const int ty = t >> 4;
    const int row0 = blockIdx.y * BM;
    const int col0 = blockIdx.x * BN;

    float acc[4][4] = {};

    for (int k0 = 0; k0 < K; k0 += BK) {
        // load A tile (64x16) and W tile (64x16), k-guarded
        #pragma unroll
        for (int i = t; i < BM * BK; i += 256) {
            int r = i >> 4, c = i & 15;
            int gk = k0 + c;
            As[c][r] = (gk < K) ? A[(size_t)(row0 + r) * K + gk] : 0.f;
        }
        #pragma unroll
        for (int i = t; i < BN * BK; i += 256) {
            int r = i >> 4, c = i & 15;
            int gk = k0 + c;
            Ws[c][r] = (gk < K) ? W[(size_t)(col0 + r) * K + gk] : 0.f;
        }
        __syncthreads();

        #pragma unroll
        for (int kk = 0; kk < BK; kk++) {
            float4 a4 = *reinterpret_cast<const float4*>(&As[kk][ty * 4]);
            float4 w4 = *reinterpret_cast<const float4*>(&Ws[kk][tx * 4]);
            float a[4] = {a4.x, a4.y, a4.z, a4.w};
            float w[4] = {w4.x, w4.y, w4.z, w4.w};
            #pragma unroll
            for (int i = 0; i < 4; i++)
                #pragma unroll
                for (int j = 0; j < 4; j++)
                    acc[i][j] = fmaf(a[i], w[j], acc[i][j]);
        }
        __syncthreads();
    }

    #pragma unroll
    for (int i = 0; i < 4; i++) {
        int gr = row0 + ty * 4 + i;
        #pragma unroll
        for (int j = 0; j < 4; j++) {
            int gn = col0 + tx * 4 + j;
            float v = acc[i][j] + (bias ? bias[gn] : 0.f);
            if (do_relu) v = fmaxf(v, 0.f);
            C[(size_t)gr * Nout + gn] = v;
        }
    }
}

// ---------------- zero scratch used with atomics ----------------
__global__ void k_zero()
{
    int idx = blockIdx.x * blockDim.x + threadIdx.x;
    if (idx < NN * MEMD) g_agg[idx] = 0.f;
    if (idx < NN * 2)    g_denom[idx] = 0.f;
}

// ---------------- build GRU input (aggr) + h + lu ----------------
__global__ __launch_bounds__(256) void k_build_aggr(
    const int* __restrict__ node_ids, const int* __restrict__ mem_last_update,
    const int* __restrict__ mem_rel_t, const int* __restrict__ mem_dst_id,
    const float* __restrict__ mem_table, const float* __restrict__ mem_msg_table,
    const float* __restrict__ mem_dir,
    const float* __restrict__ te_w, const float* __restrict__ te_b)
{
    const int n = blockIdx.x;
    const int t = threadIdx.x;
    const int nid = node_ids[n];
    const int did = mem_dst_id[nid];
    const float d0 = mem_dir[(size_t)nid * 2 + 0];
    const float d1 = mem_dir[(size_t)nid * 2 + 1];

    const float sm = mem_table[(size_t)nid * MEMD + t];
    const float dm = mem_table[(size_t)did * MEMD + t];

    float* ag = g_aggr + (size_t)n * GRUIN;
    ag[t]        = sm * d0 + dm * d1;
    ag[MEMD + t] = sm * d1 + dm * d0;
    g_h[(size_t)n * MEMD + t] = sm;

    if (t < MSGD)
        ag[2 * MEMD + t] = mem_msg_table[(size_t)nid * MSGD + t];
    if (t < TDD) {
        float rt = (float)mem_rel_t[nid];
        ag[2 * MEMD + MSGD + t] = cosf(rt * te_w[t] + te_b[t]);
    }
    if (t == 0)
        g_lu[n] = (float)mem_last_update[nid];
}

// ---------------- GRU gate combine ----------------
__global__ void k_gru()
{
    int idx = blockIdx.x * blockDim.x + threadIdx.x;   // N*MEM
    int n = idx >> 8, j = idx & 255;
    const float* gi = g_gi + (size_t)n * G3;
    const float* gh = g_gh + (size_t)n * G3;
    float r  = 1.f / (1.f + expf(-(gi[j]       + gh[j])));
    float z  = 1.f / (1.f + expf(-(gi[256 + j] + gh[256 + j])));
    float nn = tanhf(gi[512 + j] + r * gh[512 + j]);
    float h  = g_h[idx];
    g_mem[idx] = (1.f - z) * nn + z * h;
}

// ---------------- build edge attr (msg | time-enc) ----------------
__global__ void k_build_ea(
    const int* __restrict__ edge_idx, const float* __restrict__ edge_t,
    const float* __restrict__ edge_msg,
    const float* __restrict__ te_w, const float* __restrict__ te_b)
{
    const int e = blockIdx.x;
    const int t = threadIdx.x;
    if (t >= EDGED) return;
    float* ea = g_ea + (size_t)e * EDGED;
    if (t < MSGD) {
        ea[t] = edge_msg[(size_t)e * MSGD + t];
    } else {
        int src = edge_idx[e];
        float rel = g_lu[src] - edge_t[e];
        int c = t - MSGD;
        ea[t] = cosf(rel * te_w[c] + te_b[c]);
    }
}

// ---------------- attention logits -> exp, denom accumulation ----------------
// Note: reference subtracts a global per-head max inside softmax; that cancels
// exactly in e/(sum+eps). Alphas here are O(1), so plain exp is safe.
__global__ __launch_bounds__(256) void k_alpha(const int* __restrict__ edge_idx)
{
    const int e = blockIdx.x * 8 + (threadIdx.x >> 5);
    const int lane = threadIdx.x & 31;
    if (e >= EE) return;
    const int src = edge_idx[e];
    const int dst = edge_idx[EE + e];
    const float* q  = g_qn    + (size_t)dst * MEMD;
    const float* kn = g_kn    + (size_t)src * MEMD;
    const float* ep = g_eproj + (size_t)e  * MEMD;

    float a0 = 0.f, a1 = 0.f;
    #pragma unroll
    for (int c = lane; c < OCD; c += 32) {
        a0 = fmaf(q[c],       kn[c]       + ep[c],       a0);
        a1 = fmaf(q[OCD + c], kn[OCD + c] + ep[OCD + c], a1);
    }
    #pragma unroll
    for (int off = 16; off; off >>= 1) {
        a0 += __shfl_xor_sync(0xffffffffu, a0, off);
        a1 += __shfl_xor_sync(0xffffffffu, a1, off);
    }
    if (lane == 0) {
        const float inv_sqrt_oc = 0.08838834764831845f;  // 1/sqrt(128)
        float e0 = expf(a0 * inv_sqrt_oc);
        float e1 = expf(a1 * inv_sqrt_oc);
        g_expa[(size_t)e * 2 + 0] = e0;
        g_expa[(size_t)e * 2 + 1] = e1;
        atomicAdd(&g_denom[(size_t)dst * 2 + 0], e0);
        atomicAdd(&g_denom[(size_t)dst * 2 + 1], e1);
    }
}

// ---------------- weighted value scatter ----------------
__global__ __launch_bounds__(256) void k_scatter(const int* __restrict__ edge_idx)
{
    const int e = blockIdx.x;
    const int t = threadIdx.x;  // 256
    const int src = edge_idx[e];
    const int dst = edge_idx[EE + e];
    float ea_ = g_expa[(size_t)e * 2 + (t >> 7)];
    float v = (g_vn[(size_t)src * MEMD + t] + g_eproj[(size_t)e * MEMD + t]) * ea_;
    atomicAdd(&g_agg[(size_t)dst * MEMD + t], v);
}

// ---------------- z = skip + agg/denom ----------------
__global__ void k_zfin()
{
    int idx = blockIdx.x * blockDim.x + threadIdx.x;   // N*MEM
    int n = idx >> 8, c = idx & 255;
    float den = g_denom[(size_t)n * 2 + (c >> 7)] + 1e-16f;
    g_z[idx] = g_z[idx] + g_agg[idx] / den;
}

// ---------------- link predictor concat ----------------
__global__ __launch_bounds__(512) void k_cat(const int* __restrict__ node_idx)
{
    const int r = blockIdx.x;          // 0..2B-1 (pos rows then neg rows)
    const int t = threadIdx.x;         // 512
    const int b = (r < BB) ? r : r - BB;
    const int i0 = node_idx[b];
    const int i1 = (r < BB) ? node_idx[BB + b] : node_idx[2 * BB + b];
    float v = (t < 256) ? g_z[(size_t)i0 * 256 + t]
                        : g_z[(size_t)i1 * 256 + (t - 256)];
    g_cat[(size_t)r * 512 + t] = v;
}

// ---------------- final dot + mask + sigmoid ----------------
__global__ __launch_bounds__(256) void k_final(
    const int* __restrict__ node_idx, const float* __restrict__ lp_fw,
    const float* __restrict__ lp_fb, float* __restrict__ out)
{
    const int r = blockIdx.x * 8 + (threadIdx.x >> 5);
    const int lane = threadIdx.x & 31;
    if (r >= 2 * BB) return;
    const float* h = g_hid + (size_t)r * 256;
    float s = 0.f;
    #pragma unroll
    for (int c = lane; c < 256; c += 32) s = fmaf(h[c], lp_fw[c], s);
    #pragma unroll
    for (int off = 16; off; off >>= 1) s += __shfl_xor_sync(0xffffffffu, s, off);
    if (lane == 0) {
        int b = (r < BB) ? r : r - BB;
        float mask = (node_idx[b] < NN - 1) ? 1.f : 0.f;
        float val = (s + lp_fb[0]) * mask;
        out[r] = 1.f / (1.f + expf(-val));
    }
}

// ---------------- launch ----------------
extern "C" void kernel_launch(void* const* d_in, const int* in_sizes, int n_in,
                              void* d_out, int out_size)
{
    const int*   node_ids        = (const int*)  d_in[0];
    const int*   node_idx        = (const int*)  d_in[1];
    const int*   edge_idx        = (const int*)  d_in[2];
    const int*   mem_last_update = (const int*)  d_in[3];
    const int*   mem_rel_t       = (const int*)  d_in[4];
    const int*   mem_dst_id      = (const int*)  d_in[5];
    const float* edge_t          = (const float*)d_in[6];
    const float* edge_msg        = (const float*)d_in[7];
    const float* mem_table       = (const float*)d_in[8];
    const float* mem_msg_table   = (const float*)d_in[9];
    const float* mem_dir         = (const float*)d_in[10];
    const float* te_mem_w        = (const float*)d_in[11];
    const float* te_mem_b        = (const float*)d_in[12];
    const float* gru_w_ih        = (const float*)d_in[13];
    const float* gru_w_hh        = (const float*)d_in[14];
    const float* gru_b_ih        = (const float*)d_in[15];
    const float* gru_b_hh        = (const float*)d_in[16];
    const float* te_gnn_w        = (const float*)d_in[17];
    const float* te_gnn_b        = (const float*)d_in[18];
    const float* Wq              = (const float*)d_in[19];
    const float* bq              = (const float*)d_in[20];
    const float* Wk              = (const float*)d_in[21];
    const float* bk              = (const float*)d_in[22];
    const float* Wv              = (const float*)d_in[23];
    const float* bv              = (const float*)d_in[24];
    const float* We              = (const float*)d_in[25];
    const float* Wskip           = (const float*)d_in[26];
    const float* bskip           = (const float*)d_in[27];
    const float* lp_hw           = (const float*)d_in[28];
    const float* lp_hb           = (const float*)d_in[29];
    const float* lp_fw           = (const float*)d_in[30];
    const float* lp_fb           = (const float*)d_in[31];

    float *p_aggr, *p_h, *p_gi, *p_gh, *p_mem, *p_qn, *p_kn, *p_vn, *p_z,
          *p_ea, *p_eproj, *p_cat, *p_hid;
    cudaGetSymbolAddress((void**)&p_aggr,  g_aggr);
    cudaGetSymbolAddress((void**)&p_h,     g_h);
    cudaGetSymbolAddress((void**)&p_gi,    g_gi);
    cudaGetSymbolAddress((void**)&p_gh,    g_gh);
    cudaGetSymbolAddress((void**)&p_mem,   g_mem);
    cudaGetSymbolAddress((void**)&p_qn,    g_qn);
    cudaGetSymbolAddress((void**)&p_kn,    g_kn);
    cudaGetSymbolAddress((void**)&p_vn,    g_vn);
    cudaGetSymbolAddress((void**)&p_z,     g_z);
    cudaGetSymbolAddress((void**)&p_ea,    g_ea);
    cudaGetSymbolAddress((void**)&p_eproj, g_eproj);
    cudaGetSymbolAddress((void**)&p_cat,   g_cat);
    cudaGetSymbolAddress((void**)&p_hid,   g_hid);

    // reset atomic accumulators
    k_zero<<<(NN * MEMD + 255) / 256, 256>>>();

    // ---- memory (GRU) ----
    k_build_aggr<<<NN, 256>>>(node_ids, mem_last_update, mem_rel_t, mem_dst_id,
                              mem_table, mem_msg_table, mem_dir, te_mem_w, te_mem_b);
    gemm_tn<<<dim3(G3 / BN, NN / BM), 256>>>(p_aggr, gru_w_ih, gru_b_ih, p_gi,
                                             NN, G3, GRUIN, 0);
    gemm_tn<<<dim3(G3 / BN, NN / BM), 256>>>(p_h, gru_w_hh, gru_b_hh, p_gh,
                                             NN, G3, MEMD, 0);
    k_gru<<<(NN * MEMD) / 256, 256>>>();

    // ---- node projections ----
    gemm_tn<<<dim3(MEMD / BN, NN / BM), 256>>>(p_mem, Wq,    bq,    p_qn, NN, MEMD, MEMD, 0);
    gemm_tn<<<dim3(MEMD / BN, NN / BM), 256>>>(p_mem, Wk,    bk,    p_kn, NN, MEMD, MEMD, 0);
    gemm_tn<<<dim3(MEMD / BN, NN / BM), 256>>>(p_mem, Wv,    bv,    p_vn, NN, MEMD, MEMD, 0);
    gemm_tn<<<dim3(MEMD / BN, NN / BM), 256>>>(p_mem, Wskip, bskip, p_z,  NN, MEMD, MEMD, 0);

    // ---- edge attr + projection ----
    k_build_ea<<<EE, 320>>>(edge_idx, edge_t, edge_msg, te_gnn_w, te_gnn_b);
    gemm_tn<<<dim3(MEMD / BN, EE / BM), 256>>>(p_ea, We, nullptr, p_eproj,
                                               EE, MEMD, EDGED, 0);

    // ---- attention ----
    k_alpha<<<EE / 8, 256>>>(edge_idx);
    k_scatter<<<EE, 256>>>(edge_idx);
    k_zfin<<<(NN * MEMD) / 256, 256>>>();

    // ---- link predictor ----
    k_cat<<<2 * BB, 512>>>(node_idx);
    gemm_tn<<<dim3(256 / BN, (2 * BB) / BM), 256>>>(p_cat, lp_hw, lp_hb, p_hid,
                                                    2 * BB, 256, 512, 1);
    k_final<<<(2 * BB) / 8, 256>>>(node_idx, lp_fw, lp_fb, (float*)d_out);
}

// round 2
// speedup vs baseline: 1.8078x; 1.8078x over previous
#include <cuda_runtime.h>
#include <cuda_bf16.h>
#include <math.h>

// ---------------- problem constants ----------------
#define NN     16384          // nodes in batch subgraph
#define BB     4096           // events
#define EE     131072         // edges
#define MEMD   256            // memory dim
#define TDD    128            // time dim
#define MSGD   172            // raw msg dim
#define OCD    128            // per-head out channels
#define EDGED  300            // MSG + TD
#define GRUIN  812            // 2*MEM + MSG + TD
#define G3     768            // 3*MEM

// ---------------- device scratch (static; no allocs allowed) ----------------
__device__ float g_aggr[(size_t)NN * GRUIN];
__device__ float g_h   [(size_t)NN * MEMD];
__device__ float g_lu  [NN];
__device__ float g_gi  [(size_t)NN * G3];
__device__ float g_gh  [(size_t)NN * G3];
__device__ float g_mem [(size_t)NN * MEMD];
__device__ float g_qn  [(size_t)NN * MEMD];
__device__ float g_kn  [(size_t)NN * MEMD];
__device__ float g_vn  [(size_t)NN * MEMD];
__device__ float g_z   [(size_t)NN * MEMD];
__device__ float g_ea  [(size_t)EE * EDGED];
__device__ float g_eproj[(size_t)EE * MEMD];
__device__ float g_expa[(size_t)EE * 2];
__device__ float g_denom[(size_t)NN * 2];
__device__ float g_agg [(size_t)NN * MEMD];
__device__ float g_cat [(size_t)2 * BB * 512];
__device__ float g_hid [(size_t)2 * BB * 256];

// ---------------- tf32 helper ----------------
__device__ __forceinline__ unsigned f2tf32(float f) {
    unsigned r;
    asm("cvt.rna.tf32.f32 %0, %1;" : "=r"(r) : "f"(f));
    return r;
}

// ---------------- tensor-core tf32 GEMM: C = A @ W^T + bias ----------------
// A: [M,K] row-major fp32, W: [Nout,K] row-major fp32, C: [M,Nout] fp32.
// M % 128 == 0, Nout % 64 == 0, K % 4 == 0 (any K). fp32 accumulate.
// Block: 128 threads (4 warps, 2x2), block tile 128x64, warp tile 64x32.
#define TBM 128
#define TBN 64
#define TBK 16
#define AS_STRIDE 136   // 128 + 8 -> row stride = 8 mod 32 words (conflict-free frag LDS)
#define WS_STRIDE 72    // 64 + 8

__global__ __launch_bounds__(128) void gemm_tc(
    const float* __restrict__ A, const float* __restrict__ W,
    const float* __restrict__ bias, float* __restrict__ C,
    int Nout, int K, int do_relu)
{
    __shared__ unsigned As[TBK][AS_STRIDE];   // [k][m], tf32 bit patterns
    __shared__ unsigned Ws[TBK][WS_STRIDE];   // [k][n]

    const int t    = threadIdx.x;
    const int warp = t >> 5;
    const int lane = t & 31;
    const int g    = lane >> 2;   // group id (0..7)
    const int tig  = lane & 3;    // thread in group (0..3)
    const int wm   = warp >> 1;   // 0..1
    const int wn   = warp & 1;    // 0..1
    const int row0 = blockIdx.y * TBM;
    const int col0 = blockIdx.x * TBN;

    float acc[4][4][4];
    #pragma unroll
    for (int i = 0; i < 4; i++)
        #pragma unroll
        for (int j = 0; j < 4; j++)
            #pragma unroll
            for (int c = 0; c < 4; c++) acc[i][j][c] = 0.f;

    for (int k0 = 0; k0 < K; k0 += TBK) {
        // ---- stage A tile (128 rows x 16 k) : 512 float4, 4 per thread ----
        #pragma unroll
        for (int i = 0; i < 4; i++) {
            int idx = t + i * 128;               // 0..511
            int r   = idx >> 2;
            int c4  = (idx & 3) * 4;
            int kb  = k0 + c4;
            float4 v = make_float4(0.f, 0.f, 0.f, 0.f);
            if (kb < K)   // K % 4 == 0 -> full float4 in-bounds
                v = *reinterpret_cast<const float4*>(A + (size_t)(row0 + r) * K + kb);
            As[c4 + 0][r] = f2tf32(v.x);
            As[c4 + 1][r] = f2tf32(v.y);
            As[c4 + 2][r] = f2tf32(v.z);
            As[c4 + 3][r] = f2tf32(v.w);
        }
        // ---- stage W tile (64 n x 16 k) : 256 float4, 2 per thread ----
        #pragma unroll
        for (int i = 0; i < 2; i++) {
            int idx = t + i * 128;               // 0..255
            int n   = idx >> 2;
            int c4  = (idx & 3) * 4;
            int kb  = k0 + c4;
            float4 v = make_float4(0.f, 0.f, 0.f, 0.f);
            if (kb < K)
                v = *reinterpret_cast<const float4*>(W + (size_t)(col0 + n) * K + kb);
            Ws[c4 + 0][n] = f2tf32(v.x);
            Ws[c4 + 1][n] = f2tf32(v.y);
            Ws[c4 + 2][n] = f2tf32(v.z);
            Ws[c4 + 3][n] = f2tf32(v.w);
        }
        __syncthreads();

        #pragma unroll
        for (int ks = 0; ks < TBK; ks += 8) {
            unsigned af[4][4], bf[4][2];
            #pragma unroll
            for (int mt = 0; mt < 4; mt++) {
                int rb = wm * 64 + mt * 16;
                af[mt][0] = As[ks + tig    ][rb + g    ];
                af[mt][1] = As[ks + tig    ][rb + g + 8];
                af[mt][2] = As[ks + tig + 4][rb + g    ];
                af[mt][3] = As[ks + tig + 4][rb + g + 8];
            }
            #pragma unroll
            for (int nt = 0; nt < 4; nt++) {
                int nb = wn * 32 + nt * 8;
                bf[nt][0] = Ws[ks + tig    ][nb + g];
                bf[nt][1] = Ws[ks + tig + 4][nb + g];
            }
            #pragma unroll
            for (int mt = 0; mt < 4; mt++)
                #pragma unroll
                for (int nt = 0; nt < 4; nt++)
                    asm volatile(
                        "mma.sync.aligned.m16n8k8.row.col.f32.tf32.tf32.f32 "
                        "{%0,%1,%2,%3}, {%4,%5,%6,%7}, {%8,%9}, {%0,%1,%2,%3};"
                        : "+f"(acc[mt][nt][0]), "+f"(acc[mt][nt][1]),
                          "+f"(acc[mt][nt][2]), "+f"(acc[mt][nt][3])
                        : "r"(af[mt][0]), "r"(af[mt][1]),
                          "r"(af[mt][2]), "r"(af[mt][3]),
                          "r"(bf[nt][0]), "r"(bf[nt][1]));
        }
        __syncthreads();
    }

    // ---- epilogue: bias (+relu), float2 stores ----
    #pragma unroll
    for (int mt = 0; mt < 4; mt++) {
        int r_lo = row0 + wm * 64 + mt * 16 + g;
        #pragma unroll
        for (int nt = 0; nt < 4; nt++) {
            int gc = col0 + wn * 32 + nt * 8 + tig * 2;
            float b0 = bias ? bias[gc]     : 0.f;
            float b1 = bias ? bias[gc + 1] : 0.f;
            float v0 = acc[mt][nt][0] + b0;
            float v1 = acc[mt][nt][1] + b1;
            float v2 = acc[mt][nt][2] + b0;
            float v3 = acc[mt][nt][3] + b1;
            if (do_relu) {
                v0 = fmaxf(v0, 0.f); v1 = fmaxf(v1, 0.f);
                v2 = fmaxf(v2, 0.f); v3 = fmaxf(v3, 0.f);
            }
            *reinterpret_cast<float2*>(C + (size_t)r_lo * Nout + gc)       = make_float2(v0, v1);
            *reinterpret_cast<float2*>(C + (size_t)(r_lo + 8) * Nout + gc) = make_float2(v2, v3);
        }
    }
}

// ---------------- zero scratch used with atomics ----------------
__global__ void k_zero()
{
    int idx = blockIdx.x * blockDim.x + threadIdx.x;
    if (idx < NN * MEMD) g_agg[idx] = 0.f;
    if (idx < NN * 2)    g_denom[idx] = 0.f;
}

// ---------------- build GRU input (aggr) + h + lu ----------------
__global__ __launch_bounds__(256) void k_build_aggr(
    const int* __restrict__ node_ids, const int* __restrict__ mem_last_update,
    const int* __restrict__ mem_rel_t, const int* __restrict__ mem_dst_id,
    const float* __restrict__ mem_table, const float* __restrict__ mem_msg_table,
    const float* __restrict__ mem_dir,
    const float* __restrict__ te_w, const float* __restrict__ te_b)
{
    const int n = blockIdx.x;
    const int t = threadIdx.x;
    const int nid = node_ids[n];
    const int did = mem_dst_id[nid];
    const float d0 = mem_dir[(size_t)nid * 2 + 0];
    const float d1 = mem_dir[(size_t)nid * 2 + 1];

    const float sm = mem_table[(size_t)nid * MEMD + t];
    const float dm = mem_table[(size_t)did * MEMD + t];

    float* ag = g_aggr + (size_t)n * GRUIN;
    ag[t]        = sm * d0 + dm * d1;
    ag[MEMD + t] = sm * d1 + dm * d0;
    g_h[(size_t)n * MEMD + t] = sm;

    if (t < MSGD)
        ag[2 * MEMD + t] = mem_msg_table[(size_t)nid * MSGD + t];
    if (t < TDD) {
        float rt = (float)mem_rel_t[nid];
        ag[2 * MEMD + MSGD + t] = cosf(rt * te_w[t] + te_b[t]);
    }
    if (t == 0)
        g_lu[n] = (float)mem_last_update[nid];
}

// ---------------- GRU gate combine ----------------
__global__ void k_gru()
{
    int idx = blockIdx.x * blockDim.x + threadIdx.x;   // N*MEM
    int n = idx >> 8, j = idx & 255;
    const float* gi = g_gi + (size_t)n * G3;
    const float* gh = g_gh + (size_t)n * G3;
    float r  = 1.f / (1.f + expf(-(gi[j]       + gh[j])));
    float z  = 1.f / (1.f + expf(-(gi[256 + j] + gh[256 + j])));
    float nn = tanhf(gi[512 + j] + r * gh[512 + j]);
    float h  = g_h[idx];
    g_mem[idx] = (1.f - z) * nn + z * h;
}

// ---------------- build edge attr (msg | time-enc) ----------------
__global__ void k_build_ea(
    const int* __restrict__ edge_idx, const float* __restrict__ edge_t,
    const float* __restrict__ edge_msg,
    const float* __restrict__ te_w, const float* __restrict__ te_b)
{
    const int e = blockIdx.x;
    const int t = threadIdx.x;
    if (t >= EDGED) return;
    float* ea = g_ea + (size_t)e * EDGED;
    if (t < MSGD) {
        ea[t] = edge_msg[(size_t)e * MSGD + t];
    } else {
        int src = edge_idx[e];
        float rel = g_lu[src] - edge_t[e];
        int c = t - MSGD;
        ea[t] = cosf(rel * te_w[c] + te_b[c]);
    }
}

// ---------------- attention logits -> exp, denom accumulation ----------------
// Reference subtracts a global per-head max inside softmax; it cancels exactly
// in e/(sum+eps). Alphas here are O(1), so plain exp is safe.
__global__ __launch_bounds__(256) void k_alpha(const int* __restrict__ edge_idx)
{
    const int e = blockIdx.x * 8 + (threadIdx.x >> 5);
    const int lane = threadIdx.x & 31;
    if (e >= EE) return;
    const int src = edge_idx[e];
    const int dst = edge_idx[EE + e];
    const float* q  = g_qn    + (size_t)dst * MEMD;
    const float* kn = g_kn    + (size_t)src * MEMD;
    const float* ep = g_eproj + (size_t)e  * MEMD;

    float a0 = 0.f, a1 = 0.f;
    #pragma unroll
    for (int c = lane; c < OCD; c += 32) {
        a0 = fmaf(q[c],       kn[c]       + ep[c],       a0);
        a1 = fmaf(q[OCD + c], kn[OCD + c] + ep[OCD + c], a1);
    }
    #pragma unroll
    for (int off = 16; off; off >>= 1) {
        a0 += __shfl_xor_sync(0xffffffffu, a0, off);
        a1 += __shfl_xor_sync(0xffffffffu, a1, off);
    }
    if (lane == 0) {
        const float inv_sqrt_oc = 0.08838834764831845f;  // 1/sqrt(128)
        float e0 = expf(a0 * inv_sqrt_oc);
        float e1 = expf(a1 * inv_sqrt_oc);
        g_expa[(size_t)e * 2 + 0] = e0;
        g_expa[(size_t)e * 2 + 1] = e1;
        atomicAdd(&g_denom[(size_t)dst * 2 + 0], e0);
        atomicAdd(&g_denom[(size_t)dst * 2 + 1], e1);
    }
}

// ---------------- weighted value scatter ----------------
__global__ __launch_bounds__(256) void k_scatter(const int* __restrict__ edge_idx)
{
    const int e = blockIdx.x;
    const int t = threadIdx.x;  // 256
    const int src = edge_idx[e];
    const int dst = edge_idx[EE + e];
    float ea_ = g_expa[(size_t)e * 2 + (t >> 7)];
    float v = (g_vn[(size_t)src * MEMD + t] + g_eproj[(size_t)e * MEMD + t]) * ea_;
    atomicAdd(&g_agg[(size_t)dst * MEMD + t], v);
}

// ---------------- z = skip + agg/denom ----------------
__global__ void k_zfin()
{
    int idx = blockIdx.x * blockDim.x + threadIdx.x;   // N*MEM
    int n = idx >> 8, c = idx & 255;
    float den = g_denom[(size_t)n * 2 + (c >> 7)] + 1e-16f;
    g_z[idx] = g_z[idx] + g_agg[idx] / den;
}

// ---------------- link predictor concat ----------------
__global__ __launch_bounds__(512) void k_cat(const int* __restrict__ node_idx)
{
    const int r = blockIdx.x;          // 0..2B-1 (pos rows then neg rows)
    const int t = threadIdx.x;         // 512
    const int b = (r < BB) ? r : r - BB;
    const int i0 = node_idx[b];
    const int i1 = (r < BB) ? node_idx[BB + b] : node_idx[2 * BB + b];
    float v = (t < 256) ? g_z[(size_t)i0 * 256 + t]
                        : g_z[(size_t)i1 * 256 + (t - 256)];
    g_cat[(size_t)r * 512 + t] = v;
}

// ---------------- final dot + mask + sigmoid ----------------
__global__ __launch_bounds__(256) void k_final(
    const int* __restrict__ node_idx, const float* __restrict__ lp_fw,
    const float* __restrict__ lp_fb, float* __restrict__ out)
{
    const int r = blockIdx.x * 8 + (threadIdx.x >> 5);
    const int lane = threadIdx.x & 31;
    if (r >= 2 * BB) return;
    const float* h = g_hid + (size_t)r * 256;
    float s = 0.f;
    #pragma unroll
    for (int c = lane; c < 256; c += 32) s = fmaf(h[c], lp_fw[c], s);
    #pragma unroll
    for (int off = 16; off; off >>= 1) s += __shfl_xor_sync(0xffffffffu, s, off);
    if (lane == 0) {
        int b = (r < BB) ? r : r - BB;
        float mask = (node_idx[b] < NN - 1) ? 1.f : 0.f;
        float val = (s + lp_fb[0]) * mask;
        out[r] = 1.f / (1.f + expf(-val));
    }
}

// ---------------- launch ----------------
extern "C" void kernel_launch(void* const* d_in, const int* in_sizes, int n_in,
                              void* d_out, int out_size)
{
    const int*   node_ids        = (const int*)  d_in[0];
    const int*   node_idx        = (const int*)  d_in[1];
    const int*   edge_idx        = (const int*)  d_in[2];
    const int*   mem_last_update = (const int*)  d_in[3];
    const int*   mem_rel_t       = (const int*)  d_in[4];
    const int*   mem_dst_id      = (const int*)  d_in[5];
    const float* edge_t          = (const float*)d_in[6];
    const float* edge_msg        = (const float*)d_in[7];
    const float* mem_table       = (const float*)d_in[8];
    const float* mem_msg_table   = (const float*)d_in[9];
    const float* mem_dir         = (const float*)d_in[10];
    const float* te_mem_w        = (const float*)d_in[11];
    const float* te_mem_b        = (const float*)d_in[12];
    const float* gru_w_ih        = (const float*)d_in[13];
    const float* gru_w_hh        = (const float*)d_in[14];
    const float* gru_b_ih        = (const float*)d_in[15];
    const float* gru_b_hh        = (const float*)d_in[16];
    const float* te_gnn_w        = (const float*)d_in[17];
    const float* te_gnn_b        = (const float*)d_in[18];
    const float* Wq              = (const float*)d_in[19];
    const float* bq              = (const float*)d_in[20];
    const float* Wk              = (const float*)d_in[21];
    const float* bk              = (const float*)d_in[22];
    const float* Wv              = (const float*)d_in[23];
    const float* bv              = (const float*)d_in[24];
    const float* We              = (const float*)d_in[25];
    const float* Wskip           = (const float*)d_in[26];
    const float* bskip           = (const float*)d_in[27];
    const float* lp_hw           = (const float*)d_in[28];
    const float* lp_hb           = (const float*)d_in[29];
    const float* lp_fw           = (const float*)d_in[30];
    const float* lp_fb           = (const float*)d_in[31];

    float *p_aggr, *p_h, *p_gi, *p_gh, *p_mem, *p_qn, *p_kn, *p_vn, *p_z,
          *p_ea, *p_eproj, *p_cat, *p_hid;
    cudaGetSymbolAddress((void**)&p_aggr,  g_aggr);
    cudaGetSymbolAddress((void**)&p_h,     g_h);
    cudaGetSymbolAddress((void**)&p_gi,    g_gi);
    cudaGetSymbolAddress((void**)&p_gh,    g_gh);
    cudaGetSymbolAddress((void**)&p_mem,   g_mem);
    cudaGetSymbolAddress((void**)&p_qn,    g_qn);
    cudaGetSymbolAddress((void**)&p_kn,    g_kn);
    cudaGetSymbolAddress((void**)&p_vn,    g_vn);
    cudaGetSymbolAddress((void**)&p_z,     g_z);
    cudaGetSymbolAddress((void**)&p_ea,    g_ea);
    cudaGetSymbolAddress((void**)&p_eproj, g_eproj);
    cudaGetSymbolAddress((void**)&p_cat,   g_cat);
    cudaGetSymbolAddress((void**)&p_hid,   g_hid);

    // reset atomic accumulators
    k_zero<<<(NN * MEMD + 255) / 256, 256>>>();

    // ---- memory (GRU) ----
    k_build_aggr<<<NN, 256>>>(node_ids, mem_last_update, mem_rel_t, mem_dst_id,
                              mem_table, mem_msg_table, mem_dir, te_mem_w, te_mem_b);
    gemm_tc<<<dim3(G3 / TBN, NN / TBM), 128>>>(p_aggr, gru_w_ih, gru_b_ih, p_gi,
                                               G3, GRUIN, 0);
    gemm_tc<<<dim3(G3 / TBN, NN / TBM), 128>>>(p_h, gru_w_hh, gru_b_hh, p_gh,
                                               G3, MEMD, 0);
    k_gru<<<(NN * MEMD) / 256, 256>>>();

    // ---- node projections ----
    gemm_tc<<<dim3(MEMD / TBN, NN / TBM), 128>>>(p_mem, Wq,    bq,    p_qn, MEMD, MEMD, 0);
    gemm_tc<<<dim3(MEMD / TBN, NN / TBM), 128>>>(p_mem, Wk,    bk,    p_kn, MEMD, MEMD, 0);
    gemm_tc<<<dim3(MEMD / TBN, NN / TBM), 128>>>(p_mem, Wv,    bv,    p_vn, MEMD, MEMD, 0);
    gemm_tc<<<dim3(MEMD / TBN, NN / TBM), 128>>>(p_mem, Wskip, bskip, p_z,  MEMD, MEMD, 0);

    // ---- edge attr + projection ----
    k_build_ea<<<EE, 320>>>(edge_idx, edge_t, edge_msg, te_gnn_w, te_gnn_b);
    gemm_tc<<<dim3(MEMD / TBN, EE / TBM), 128>>>(p_ea, We, nullptr, p_eproj,
                                                 MEMD, EDGED, 0);

    // ---- attention ----
    k_alpha<<<EE / 8, 256>>>(edge_idx);
    k_scatter<<<EE, 256>>>(edge_idx);
    k_zfin<<<(NN * MEMD) / 256, 256>>>();

    // ---- link predictor ----
    k_cat<<<2 * BB, 512>>>(node_idx);
    gemm_tc<<<dim3(256 / TBN, (2 * BB) / TBM), 128>>>(p_cat, lp_hw, lp_hb, p_hid,
                                                      256, 512, 1);
    k_final<<<(2 * BB) / 8, 256>>>(node_idx, lp_fw, lp_fb, (float*)d_out);
}

// round 3
// speedup vs baseline: 2.6873x; 1.4865x over previous
#include <cuda_runtime.h>
#include <math.h>

// ---------------- problem constants ----------------
#define NN     16384
#define BB     4096
#define EE     131072
#define MEMD   256
#define TDD    128
#define MSGD   172
#define EDGED  300
#define GRUIN  812
#define G3     768

// ---------------- device scratch ----------------
__device__ float g_aggr [(size_t)NN * GRUIN];
__device__ float g_h    [(size_t)NN * MEMD];
__device__ float g_lu   [NN];
__device__ float g_gi   [(size_t)NN * G3];
__device__ float g_gh   [(size_t)NN * G3];
__device__ float g_mem  [(size_t)NN * MEMD];
__device__ float g_qkvs [(size_t)NN * 1024];   // [q | k | v | skip]
__device__ float g_te   [(size_t)EE * TDD];
__device__ float g_eproj[(size_t)EE * MEMD];
__device__ float g_denom[(size_t)NN * 2];
__device__ float g_agg  [(size_t)NN * MEMD];
__device__ float g_z    [(size_t)NN * MEMD];
__device__ float g_hid  [(size_t)2 * BB * 256];

__device__ __forceinline__ unsigned f2tf32(float f) {
    unsigned r;
    asm("cvt.rna.tf32.f32 %0, %1;" : "=r"(r) : "f"(f));
    return r;
}

// ================= tf32 tensor-core GEMM, double-buffered =================
// C[M,Nout] = A[M,K] @ W[Nout,K]^T + bias.  M%128==0, Nout%128==0, K%4==0.
// 256 threads (8 warps, 2x4), block tile 128x128, warp tile 64x32.
// MODE 0: plain A.   MODE 1: A split (edge_msg | te).   MODE 2: gathered
// link-pred rows from g_z.   MODE 3: 4 stacked weight matrices (q,k,v,skip).
#define TBM 128
#define TBN 128
#define TBK 16
#define KPAD 20   // 16 + 4; 20g+tig bijective mod 32 -> conflict-free frag LDS

template<int MODE>
__global__ __launch_bounds__(256) void gemm3(
    const float* __restrict__ A, const float* __restrict__ A2,
    const int* __restrict__ gidx,
    const float* __restrict__ W0c, const float* __restrict__ W1c,
    const float* __restrict__ W2c, const float* __restrict__ W3c,
    const float* __restrict__ b0c, const float* __restrict__ b1c,
    const float* __restrict__ b2c, const float* __restrict__ b3c,
    float* __restrict__ C, int Nout, int K, int do_relu)
{
    __shared__ unsigned As[2][TBM][KPAD];
    __shared__ unsigned Ws[2][TBN][KPAD];

    const int t    = threadIdx.x;
    const int warp = t >> 5;
    const int lane = t & 31;
    const int g    = lane >> 2;
    const int tig  = lane & 3;
    const int wm   = warp >> 2;   // 0..1
    const int wn   = warp & 3;    // 0..3
    const int row0 = blockIdx.y * TBM;
    const int col0 = blockIdx.x * TBN;

    const float* Wsel = W0c;
    const float* bsel = b0c;
    int colL = col0;
    if (MODE == 3) {
        int grp = col0 >> 8;
        Wsel = (grp == 0) ? W0c : (grp == 1) ? W1c : (grp == 2) ? W2c : W3c;
        bsel = (grp == 0) ? b0c : (grp == 1) ? b1c : (grp == 2) ? b2c : b3c;
        colL = col0 & 255;
    }

    float acc[4][4][4];
    #pragma unroll
    for (int i = 0; i < 4; i++)
        #pragma unroll
        for (int j = 0; j < 4; j++)
            #pragma unroll
            for (int c = 0; c < 4; c++) acc[i][j][c] = 0.f;

    auto ldA = [&](int idx, int k0) -> float4 {
        int r  = idx >> 2;
        int kb = k0 + (idx & 3) * 4;
        if (kb >= K) return make_float4(0.f, 0.f, 0.f, 0.f);
        int gr = row0 + r;
        if (MODE == 1)
            return (kb < MSGD)
                ? *(const float4*)(A  + (size_t)gr * MSGD + kb)
                : *(const float4*)(A2 + (size_t)gr * TDD  + (kb - MSGD));
        if (MODE == 2) {
            int b = gr & (BB - 1), side = gr >> 12;
            int i   = (kb < 256) ? gidx[b] : gidx[BB + side * BB + b];
            int off = (kb < 256) ? kb : kb - 256;
            return *(const float4*)(A + (size_t)i * 256 + off);
        }
        return *(const float4*)(A + (size_t)gr * K + kb);
    };
    auto ldW = [&](int idx, int k0) -> float4 {
        int n  = idx >> 2;
        int kb = k0 + (idx & 3) * 4;
        if (kb >= K) return make_float4(0.f, 0.f, 0.f, 0.f);
        return *(const float4*)(Wsel + (size_t)(colL + n) * K + kb);
    };
    auto store = [&](int buf, const float4* ra, const float4* rw) {
        #pragma unroll
        for (int i = 0; i < 2; i++) {
            int idx = t + i * 256;
            int r = idx >> 2, c4 = (idx & 3) * 4;
            As[buf][r][c4 + 0] = f2tf32(ra[i].x);
            As[buf][r][c4 + 1] = f2tf32(ra[i].y);
            As[buf][r][c4 + 2] = f2tf32(ra[i].z);
            As[buf][r][c4 + 3] = f2tf32(ra[i].w);
            Ws[buf][r][c4 + 0] = f2tf32(rw[i].x);
            Ws[buf][r][c4 + 1] = f2tf32(rw[i].y);
            Ws[buf][r][c4 + 2] = f2tf32(rw[i].z);
            Ws[buf][r][c4 + 3] = f2tf32(rw[i].w);
        }
    };
    auto compute = [&](int buf) {
        #pragma unroll
        for (int ks = 0; ks < TBK; ks += 8) {
            unsigned af[4][4], bf[4][2];
            #pragma unroll
            for (int mt = 0; mt < 4; mt++) {
                int rb = wm * 64 + mt * 16;
                af[mt][0] = As[buf][rb + g    ][ks + tig];
                af[mt][1] = As[buf][rb + g + 8][ks + tig];
                af[mt][2] = As[buf][rb + g    ][ks + tig + 4];
                af[mt][3] = As[buf][rb + g + 8][ks + tig + 4];
            }
            #pragma unroll
            for (int nt = 0; nt < 4; nt++) {
                int nb = wn * 32 + nt * 8;
                bf[nt][0] = Ws[buf][nb + g][ks + tig];
                bf[nt][1] = Ws[buf][nb + g][ks + tig + 4];
            }
            #pragma unroll
            for (int mt = 0; mt < 4; mt++)
                #pragma unroll
                for (int nt = 0; nt < 4; nt++)
                    asm volatile(
                        "mma.sync.aligned.m16n8k8.row.col.f32.tf32.tf32.f32 "
                        "{%0,%1,%2,%3}, {%4,%5,%6,%7}, {%8,%9}, {%0,%1,%2,%3};"
                        : "+f"(acc[mt][nt][0]), "+f"(acc[mt][nt][1]),
                          "+f"(acc[mt][nt][2]), "+f"(acc[mt][nt][3])
                        : "r"(af[mt][0]), "r"(af[mt][1]),
                          "r"(af[mt][2]), "r"(af[mt][3]),
                          "r"(bf[nt][0]), "r"(bf[nt][1]));
        }
    };

    float4 ra[2], rw[2];
    #pragma unroll
    for (int i = 0; i < 2; i++) { ra[i] = ldA(t + i * 256, 0); rw[i] = ldW(t + i * 256, 0); }
    store(0, ra, rw);
    __syncthreads();

    int cur = 0;
    for (int k0 = TBK; k0 < K; k0 += TBK) {
        #pragma unroll
        for (int i = 0; i < 2; i++) { ra[i] = ldA(t + i * 256, k0); rw[i] = ldW(t + i * 256, k0); }
        compute(cur);
        __syncthreads();
        store(cur ^ 1, ra, rw);
        __syncthreads();
        cur ^= 1;
    }
    compute(cur);

    #pragma unroll
    for (int mt = 0; mt < 4; mt++) {
        int gr = row0 + wm * 64 + mt * 16 + g;
        #pragma unroll
        for (int nt = 0; nt < 4; nt++) {
            int nl = colL + wn * 32 + nt * 8 + tig * 2;   // bias index (local)
            int gc = col0 + wn * 32 + nt * 8 + tig * 2;   // output column
            float bb0 = bsel ? bsel[nl]     : 0.f;
            float bb1 = bsel ? bsel[nl + 1] : 0.f;
            float v0 = acc[mt][nt][0] + bb0;
            float v1 = acc[mt][nt][1] + bb1;
            float v2 = acc[mt][nt][2] + bb0;
            float v3 = acc[mt][nt][3] + bb1;
            if (do_relu) {
                v0 = fmaxf(v0, 0.f); v1 = fmaxf(v1, 0.f);
                v2 = fmaxf(v2, 0.f); v3 = fmaxf(v3, 0.f);
            }
            *reinterpret_cast<float2*>(C + (size_t)gr * Nout + gc)       = make_float2(v0, v1);
            *reinterpret_cast<float2*>(C + (size_t)(gr + 8) * Nout + gc) = make_float2(v2, v3);
        }
    }
}

// ---------------- zero atomic accumulators ----------------
__global__ void k_zero()
{
    int i = blockIdx.x * blockDim.x + threadIdx.x;   // 0 .. NN*64-1
    float4 z = make_float4(0.f, 0.f, 0.f, 0.f);
    if (i < NN * 64) ((float4*)g_agg)[i] = z;
    if (i < NN / 2)  ((float4*)g_denom)[i] = z;
}

// ---------------- build GRU input (warp per node) ----------------
__global__ __launch_bounds__(256) void k_build_aggr(
    const int* __restrict__ node_ids, const int* __restrict__ mem_last_update,
    const int* __restrict__ mem_rel_t, const int* __restrict__ mem_dst_id,
    const float* __restrict__ mem_table, const float* __restrict__ mem_msg_table,
    const float* __restrict__ mem_dir,
    const float* __restrict__ te_w, const float* __restrict__ te_b)
{
    const int lane = threadIdx.x & 31;
    const int nwarps = gridDim.x * 8;
    const float4 w4 = ((const float4*)te_w)[lane];
    const float4 b4 = ((const float4*)te_b)[lane];
    for (int n = blockIdx.x * 8 + (threadIdx.x >> 5); n < NN; n += nwarps) {
        const int nid = node_ids[n];
        const int did = mem_dst_id[nid];
        const float d0 = mem_dir[2 * nid], d1 = mem_dir[2 * nid + 1];
        const float4* sm4 = (const float4*)(mem_table + (size_t)nid * MEMD);
        const float4* dm4 = (const float4*)(mem_table + (size_t)did * MEMD);
        float4* ag = (float4*)(g_aggr + (size_t)n * GRUIN);
        float4* hh = (float4*)(g_h + (size_t)n * MEMD);
        #pragma unroll
        for (int i = 0; i < 2; i++) {
            int j = lane + i * 32;
            float4 s = sm4[j], d = dm4[j];
            ag[j]      = make_float4(s.x*d0 + d.x*d1, s.y*d0 + d.y*d1,
                                     s.z*d0 + d.z*d1, s.w*d0 + d.w*d1);
            ag[64 + j] = make_float4(s.x*d1 + d.x*d0, s.y*d1 + d.y*d0,
                                     s.z*d1 + d.z*d0, s.w*d1 + d.w*d0);
            hh[j] = s;
        }
        const float4* mg = (const float4*)(mem_msg_table + (size_t)nid * MSGD);
        for (int j = lane; j < MSGD / 4; j += 32) ag[128 + j] = mg[j];
        float rt = (float)mem_rel_t[nid];
        ag[171 + lane] = make_float4(cosf(rt * w4.x + b4.x), cosf(rt * w4.y + b4.y),
                                     cosf(rt * w4.z + b4.z), cosf(rt * w4.w + b4.w));
        if (lane == 0) g_lu[n] = (float)mem_last_update[nid];
    }
}

// ---------------- GRU gate combine (float4) ----------------
__global__ void k_gru()
{
    int i4 = blockIdx.x * blockDim.x + threadIdx.x;   // NN*64
    if (i4 >= NN * 64) return;
    int n = i4 >> 6, c4 = (i4 & 63) * 4;
    const float* gi = g_gi + (size_t)n * G3;
    const float* gh = g_gh + (size_t)n * G3;
    float4 ir = *(const float4*)(gi + c4);
    float4 iz = *(const float4*)(gi + 256 + c4);
    float4 in_ = *(const float4*)(gi + 512 + c4);
    float4 hr = *(const float4*)(gh + c4);
    float4 hz = *(const float4*)(gh + 256 + c4);
    float4 hn = *(const float4*)(gh + 512 + c4);
    float4 hv = *(const float4*)(g_h + (size_t)n * MEMD + c4);
    float4 o;
    {
        float r = 1.f/(1.f+expf(-(ir.x+hr.x))), z = 1.f/(1.f+expf(-(iz.x+hz.x)));
        o.x = (1.f-z)*tanhf(in_.x + r*hn.x) + z*hv.x;
    }{
        float r = 1.f/(1.f+expf(-(ir.y+hr.y))), z = 1.f/(1.f+expf(-(iz.y+hz.y)));
        o.y = (1.f-z)*tanhf(in_.y + r*hn.y) + z*hv.y;
    }{
        float r = 1.f/(1.f+expf(-(ir.z+hr.z))), z = 1.f/(1.f+expf(-(iz.z+hz.z)));
        o.z = (1.f-z)*tanhf(in_.z + r*hn.z) + z*hv.z;
    }{
        float r = 1.f/(1.f+expf(-(ir.w+hr.w))), z = 1.f/(1.f+expf(-(iz.w+hz.w)));
        o.w = (1.f-z)*tanhf(in_.w + r*hn.w) + z*hv.w;
    }
    *(float4*)(g_mem + (size_t)n * MEMD + c4) = o;
}

// ---------------- edge time-encoding only (msg fused into GEMM) ----------------
__global__ __launch_bounds__(256) void k_build_te(
    const int* __restrict__ edge_idx, const float* __restrict__ edge_t,
    const float* __restrict__ te_w, const float* __restrict__ te_b)
{
    const int lane = threadIdx.x & 31;
    const int nwarps = gridDim.x * 8;
    const float4 w4 = ((const float4*)te_w)[lane];
    const float4 b4 = ((const float4*)te_b)[lane];
    for (int e = blockIdx.x * 8 + (threadIdx.x >> 5); e < EE; e += nwarps) {
        float rel = g_lu[edge_idx[e]] - edge_t[e];
        ((float4*)(g_te + (size_t)e * TDD))[lane] =
            make_float4(cosf(rel * w4.x + b4.x), cosf(rel * w4.y + b4.y),
                        cosf(rel * w4.z + b4.z), cosf(rel * w4.w + b4.w));
    }
}

// ---------------- fused attention: logits + exp + denom + value scatter ----------------
// Reference subtracts a global per-head max in softmax; it cancels exactly in
// e/(sum+eps). Logits here are O(1), so plain exp is safe.
__global__ __launch_bounds__(256) void k_attn(const int* __restrict__ edge_idx)
{
    const int lane = threadIdx.x & 31;
    const int nwarps = gridDim.x * 8;
    const float scal = 0.08838834764831845f;   // 1/sqrt(128)
    for (int e = blockIdx.x * 8 + (threadIdx.x >> 5); e < EE; e += nwarps) {
        const int src = edge_idx[e];
        const int dst = edge_idx[EE + e];
        const float4* ep4 = (const float4*)(g_eproj + (size_t)e * 256);
        const float4* q4  = (const float4*)(g_qkvs + (size_t)dst * 1024);
        const float4* k4  = (const float4*)(g_qkvs + (size_t)src * 1024 + 256);
        float4 e0 = ep4[lane], e1 = ep4[32 + lane];
        float4 q0 = q4[lane],  q1 = q4[32 + lane];
        float4 kk0 = k4[lane], kk1 = k4[32 + lane];
        float a0 = q0.x*(kk0.x+e0.x) + q0.y*(kk0.y+e0.y) + q0.z*(kk0.z+e0.z) + q0.w*(kk0.w+e0.w);
        float a1 = q1.x*(kk1.x+e1.x) + q1.y*(kk1.y+e1.y) + q1.z*(kk1.z+e1.z) + q1.w*(kk1.w+e1.w);
        #pragma unroll
        for (int o = 16; o; o >>= 1) {
            a0 += __shfl_xor_sync(0xffffffffu, a0, o);
            a1 += __shfl_xor_sync(0xffffffffu, a1, o);
        }
        float x0 = expf(a0 * scal);
        float x1 = expf(a1 * scal);
        if (lane == 0) {
            atomicAdd(&g_denom[2 * dst + 0], x0);
            atomicAdd(&g_denom[2 * dst + 1], x1);
        }
        const float4* v4 = (const float4*)(g_qkvs + (size_t)src * 1024 + 512);
        float4 v0 = v4[lane], v1 = v4[32 + lane];
        float* agg = g_agg + (size_t)dst * 256;
        int c = 4 * lane;
        atomicAdd(&agg[c + 0], (v0.x + e0.x) * x0);
        atomicAdd(&agg[c + 1], (v0.y + e0.y) * x0);
        atomicAdd(&agg[c + 2], (v0.z + e0.z) * x0);
        atomicAdd(&agg[c + 3], (v0.w + e0.w) * x0);
        atomicAdd(&agg[128 + c + 0], (v1.x + e1.x) * x1);
        atomicAdd(&agg[128 + c + 1], (v1.y + e1.y) * x1);
        atomicAdd(&agg[128 + c + 2], (v1.z + e1.z) * x1);
        atomicAdd(&agg[128 + c + 3], (v1.w + e1.w) * x1);
    }
}

// ---------------- z = skip + agg/denom ----------------
__global__ void k_zfin()
{
    int i4 = blockIdx.x * blockDim.x + threadIdx.x;   // NN*64
    if (i4 >= NN * 64) return;
    int n = i4 >> 6, c4 = (i4 & 63) * 4;
    float rinv = 1.f / (g_denom[2 * n + (c4 >> 7)] + 1e-16f);
    float4 a  = *(const float4*)(g_agg + (size_t)n * 256 + c4);
    float4 sk = *(const float4*)(g_qkvs + (size_t)n * 1024 + 768 + c4);
    *(float4*)(g_z + (size_t)n * 256 + c4) =
        make_float4(sk.x + a.x * rinv, sk.y + a.y * rinv,
                    sk.z + a.z * rinv, sk.w + a.w * rinv);
}

// ---------------- final dot + mask + sigmoid ----------------
__global__ __launch_bounds__(256) void k_final(
    const int* __restrict__ node_idx, const float* __restrict__ lp_fw,
    const float* __restrict__ lp_fb, float* __restrict__ out)
{
    const int r = blockIdx.x * 8 + (threadIdx.x >> 5);
    const int lane = threadIdx.x & 31;
    if (r >= 2 * BB) return;
    const float4* h4 = (const float4*)(g_hid + (size_t)r * 256);
    const float4* w4 = (const float4*)lp_fw;
    float4 a = h4[lane], b = w4[lane];
    float4 a2 = h4[32 + lane], b2 = w4[32 + lane];
    float s = a.x*b.x + a.y*b.y + a.z*b.z + a.w*b.w
            + a2.x*b2.x + a2.y*b2.y + a2.z*b2.z + a2.w*b2.w;
    #pragma unroll
    for (int o = 16; o; o >>= 1) s += __shfl_xor_sync(0xffffffffu, s, o);
    if (lane == 0) {
        int bidx = r & (BB - 1);
        float mask = (node_idx[bidx] < NN - 1) ? 1.f : 0.f;
        float val = (s + lp_fb[0]) * mask;
        out[r] = 1.f / (1.f + expf(-val));
    }
}

// ---------------- launch ----------------
extern "C" void kernel_launch(void* const* d_in, const int* in_sizes, int n_in,
                              void* d_out, int out_size)
{
    const int*   node_ids        = (const int*)  d_in[0];
    const int*   node_idx        = (const int*)  d_in[1];
    const int*   edge_idx        = (const int*)  d_in[2];
    const int*   mem_last_update = (const int*)  d_in[3];
    const int*   mem_rel_t       = (const int*)  d_in[4];
    const int*   mem_dst_id      = (const int*)  d_in[5];
    const float* edge_t          = (const float*)d_in[6];
    const float* edge_msg        = (const float*)d_in[7];
    const float* mem_table       = (const float*)d_in[8];
    const float* mem_msg_table   = (const float*)d_in[9];
    const float* mem_dir         = (const float*)d_in[10];
    const float* te_mem_w        = (const float*)d_in[11];
    const float* te_mem_b        = (const float*)d_in[12];
    const float* gru_w_ih        = (const float*)d_in[13];
    const float* gru_w_hh        = (const float*)d_in[14];
    const float* gru_b_ih        = (const float*)d_in[15];
    const float* gru_b_hh        = (const float*)d_in[16];
    const float* te_gnn_w        = (const float*)d_in[17];
    const float* te_gnn_b        = (const float*)d_in[18];
    const float* Wq              = (const float*)d_in[19];
    const float* bq              = (const float*)d_in[20];
    const float* Wk              = (const float*)d_in[21];
    const float* bk              = (const float*)d_in[22];
    const float* Wv              = (const float*)d_in[23];
    const float* bv              = (const float*)d_in[24];
    const float* We              = (const float*)d_in[25];
    const float* Wskip           = (const float*)d_in[26];
    const float* bskip           = (const float*)d_in[27];
    const float* lp_hw           = (const float*)d_in[28];
    const float* lp_hb           = (const float*)d_in[29];
    const float* lp_fw           = (const float*)d_in[30];
    const float* lp_fb           = (const float*)d_in[31];

    float *p_aggr, *p_h, *p_gi, *p_gh, *p_mem, *p_qkvs, *p_te, *p_eproj,
          *p_z, *p_hid;
    cudaGetSymbolAddress((void**)&p_aggr,  g_aggr);
    cudaGetSymbolAddress((void**)&p_h,     g_h);
    cudaGetSymbolAddress((void**)&p_gi,    g_gi);
    cudaGetSymbolAddress((void**)&p_gh,    g_gh);
    cudaGetSymbolAddress((void**)&p_mem,   g_mem);
    cudaGetSymbolAddress((void**)&p_qkvs,  g_qkvs);
    cudaGetSymbolAddress((void**)&p_te,    g_te);
    cudaGetSymbolAddress((void**)&p_eproj, g_eproj);
    cudaGetSymbolAddress((void**)&p_z,     g_z);
    cudaGetSymbolAddress((void**)&p_hid,   g_hid);

    k_zero<<<4096, 256>>>();

    // ---- memory (GRU) ----
    k_build_aggr<<<2048, 256>>>(node_ids, mem_last_update, mem_rel_t, mem_dst_id,
                                mem_table, mem_msg_table, mem_dir, te_mem_w, te_mem_b);
    gemm3<0><<<dim3(G3 / TBN, NN / TBM), 256>>>(
        p_aggr, nullptr, nullptr,
        gru_w_ih, nullptr, nullptr, nullptr,
        gru_b_ih, nullptr, nullptr, nullptr,
        p_gi, G3, GRUIN, 0);
    gemm3<0><<<dim3(G3 / TBN, NN / TBM), 256>>>(
        p_h, nullptr, nullptr,
        gru_w_hh, nullptr, nullptr, nullptr,
        gru_b_hh, nullptr, nullptr, nullptr,
        p_gh, G3, MEMD, 0);
    k_gru<<<4096, 256>>>();

    // ---- fused q|k|v|skip projection ----
    gemm3<3><<<dim3(1024 / TBN, NN / TBM), 256>>>(
        p_mem, nullptr, nullptr,
        Wq, Wk, Wv, Wskip,
        bq, bk, bv, bskip,
        p_qkvs, 1024, MEMD, 0);

    // ---- edge projection (msg columns read directly from input) ----
    k_build_te<<<2048, 256>>>(edge_idx, edge_t, te_gnn_w, te_gnn_b);
    gemm3<1><<<dim3(MEMD / TBN, EE / TBM), 256>>>(
        edge_msg, p_te, nullptr,
        We, nullptr, nullptr, nullptr,
        nullptr, nullptr, nullptr, nullptr,
        p_eproj, MEMD, EDGED, 0);

    // ---- fused attention + scatter ----
    k_attn<<<2048, 256>>>(edge_idx);
    k_zfin<<<4096, 256>>>();

    // ---- link predictor (gather fused into GEMM A-stage) ----
    gemm3<2><<<dim3(MEMD / TBN, (2 * BB) / TBM), 256>>>(
        p_z, nullptr, node_idx,
        lp_hw, nullptr, nullptr, nullptr,
        lp_hb, nullptr, nullptr, nullptr,
        p_hid, MEMD, 2 * MEMD, 1);
    k_final<<<1024, 256>>>(node_idx, lp_fw, lp_fb, (float*)d_out);
}

// round 4
// speedup vs baseline: 2.9309x; 1.0906x over previous
#include <cuda_runtime.h>
#include <math.h>

// ---------------- problem constants ----------------
#define NN     16384
#define BB     4096
#define EE     131072
#define MEMD   256
#define TDD    128
#define MSGD   172
#define EDGED  300
#define GRUIN  812
#define G3     768

// ---------------- device scratch ----------------
__device__ float g_aggr [(size_t)NN * GRUIN];
__device__ float g_h    [(size_t)NN * MEMD];
__device__ float g_lu   [NN];
__device__ float g_gi   [(size_t)NN * G3];
__device__ float g_gh   [(size_t)NN * G3];
__device__ float g_mem  [(size_t)NN * MEMD];
__device__ float g_qkvs [(size_t)NN * 1024];   // [q | k | v | skip]
__device__ float g_te   [(size_t)EE * TDD];
__device__ float g_denom[(size_t)NN * 2];
__device__ float g_agg  [(size_t)NN * MEMD];
__device__ float g_z    [(size_t)NN * MEMD];
__device__ float g_hid  [(size_t)2 * BB * 256];

__device__ __forceinline__ unsigned f2tf32(float f) {
    unsigned r;
    asm("cvt.rna.tf32.f32 %0, %1;" : "=r"(r) : "f"(f));
    return r;
}

#define TBM 128
#define TBN 128
#define TBK 16
#define KPAD 20

#define MMA_TF32(acc, af, bf)                                              \
    asm volatile(                                                          \
        "mma.sync.aligned.m16n8k8.row.col.f32.tf32.tf32.f32 "              \
        "{%0,%1,%2,%3}, {%4,%5,%6,%7}, {%8,%9}, {%0,%1,%2,%3};"            \
        : "+f"(acc[0]), "+f"(acc[1]), "+f"(acc[2]), "+f"(acc[3])           \
        : "r"(af[0]), "r"(af[1]), "r"(af[2]), "r"(af[3]),                  \
          "r"(bf[0]), "r"(bf[1]))

// ================= generic tf32 GEMM (modes 0/2/3) =================
// C[M,Nout] = A[M,K] @ W[Nout,K]^T + bias. Single-sync double buffer.
template<int MODE>
__global__ __launch_bounds__(256) void gemm3(
    const float* __restrict__ A, const int* __restrict__ gidx,
    const float* __restrict__ W0c, const float* __restrict__ W1c,
    const float* __restrict__ W2c, const float* __restrict__ W3c,
    const float* __restrict__ b0c, const float* __restrict__ b1c,
    const float* __restrict__ b2c, const float* __restrict__ b3c,
    float* __restrict__ C, int Nout, int K, int do_relu)
{
    __shared__ unsigned As[2][TBM][KPAD];
    __shared__ unsigned Ws[2][TBN][KPAD];

    const int t    = threadIdx.x;
    const int warp = t >> 5;
    const int lane = t & 31;
    const int g    = lane >> 2;
    const int tig  = lane & 3;
    const int wm   = warp >> 2;
    const int wn   = warp & 3;
    const int row0 = blockIdx.y * TBM;
    const int col0 = blockIdx.x * TBN;

    const float* Wsel = W0c;
    const float* bsel = b0c;
    int colL = col0;
    if (MODE == 3) {
        int grp = col0 >> 8;
        Wsel = (grp == 0) ? W0c : (grp == 1) ? W1c : (grp == 2) ? W2c : W3c;
        bsel = (grp == 0) ? b0c : (grp == 1) ? b1c : (grp == 2) ? b2c : b3c;
        colL = col0 & 255;
    }

    float acc[4][4][4];
    #pragma unroll
    for (int i = 0; i < 4; i++)
        #pragma unroll
        for (int j = 0; j < 4; j++)
            #pragma unroll
            for (int c = 0; c < 4; c++) acc[i][j][c] = 0.f;

    auto ldA = [&](int idx, int k0) -> float4 {
        int r  = idx >> 2;
        int kb = k0 + (idx & 3) * 4;
        if (kb >= K) return make_float4(0.f, 0.f, 0.f, 0.f);
        int gr = row0 + r;
        if (MODE == 2) {
            int b = gr & (BB - 1), side = gr >> 12;
            int i   = (kb < 256) ? gidx[b] : gidx[BB + side * BB + b];
            int off = (kb < 256) ? kb : kb - 256;
            return *(const float4*)(A + (size_t)i * 256 + off);
        }
        return *(const float4*)(A + (size_t)gr * K + kb);
    };
    auto ldW = [&](int idx, int k0) -> float4 {
        int n  = idx >> 2;
        int kb = k0 + (idx & 3) * 4;
        if (kb >= K) return make_float4(0.f, 0.f, 0.f, 0.f);
        return *(const float4*)(Wsel + (size_t)(colL + n) * K + kb);
    };
    auto store = [&](int buf, const float4* ra, const float4* rw) {
        #pragma unroll
        for (int i = 0; i < 2; i++) {
            int idx = t + i * 256;
            int r = idx >> 2, c4 = (idx & 3) * 4;
            As[buf][r][c4 + 0] = f2tf32(ra[i].x);
            As[buf][r][c4 + 1] = f2tf32(ra[i].y);
            As[buf][r][c4 + 2] = f2tf32(ra[i].z);
            As[buf][r][c4 + 3] = f2tf32(ra[i].w);
            Ws[buf][r][c4 + 0] = f2tf32(rw[i].x);
            Ws[buf][r][c4 + 1] = f2tf32(rw[i].y);
            Ws[buf][r][c4 + 2] = f2tf32(rw[i].z);
            Ws[buf][r][c4 + 3] = f2tf32(rw[i].w);
        }
    };
    auto compute = [&](int buf) {
        #pragma unroll
        for (int ks = 0; ks < TBK; ks += 8) {
            unsigned af[4][4], bf[4][2];
            #pragma unroll
            for (int mt = 0; mt < 4; mt++) {
                int rb = wm * 64 + mt * 16;
                af[mt][0] = As[buf][rb + g    ][ks + tig];
                af[mt][1] = As[buf][rb + g + 8][ks + tig];
                af[mt][2] = As[buf][rb + g    ][ks + tig + 4];
                af[mt][3] = As[buf][rb + g + 8][ks + tig + 4];
            }
            #pragma unroll
            for (int nt = 0; nt < 4; nt++) {
                int nb = wn * 32 + nt * 8;
                bf[nt][0] = Ws[buf][nb + g][ks + tig];
                bf[nt][1] = Ws[buf][nb + g][ks + tig + 4];
            }
            #pragma unroll
            for (int mt = 0; mt < 4; mt++)
                #pragma unroll
                for (int nt = 0; nt < 4; nt++)
                    MMA_TF32(acc[mt][nt], af[mt], bf[nt]);
        }
    };

    float4 ra[2], rw[2];
    #pragma unroll
    for (int i = 0; i < 2; i++) { ra[i] = ldA(t + i * 256, 0); rw[i] = ldW(t + i * 256, 0); }
    store(0, ra, rw);
    __syncthreads();

    int cur = 0;
    for (int k0 = TBK; k0 < K; k0 += TBK) {
        #pragma unroll
        for (int i = 0; i < 2; i++) { ra[i] = ldA(t + i * 256, k0); rw[i] = ldW(t + i * 256, k0); }
        compute(cur);
        store(cur ^ 1, ra, rw);   // disjoint buffer; prev-iter sync protects it
        __syncthreads();
        cur ^= 1;
    }
    compute(cur);

    #pragma unroll
    for (int mt = 0; mt < 4; mt++) {
        int gr = row0 + wm * 64 + mt * 16 + g;
        #pragma unroll
        for (int nt = 0; nt < 4; nt++) {
            int nl = colL + wn * 32 + nt * 8 + tig * 2;
            int gc = col0 + wn * 32 + nt * 8 + tig * 2;
            float bb0 = bsel ? bsel[nl]     : 0.f;
            float bb1 = bsel ? bsel[nl + 1] : 0.f;
            float v0 = acc[mt][nt][0] + bb0;
            float v1 = acc[mt][nt][1] + bb1;
            float v2 = acc[mt][nt][2] + bb0;
            float v3 = acc[mt][nt][3] + bb1;
            if (do_relu) {
                v0 = fmaxf(v0, 0.f); v1 = fmaxf(v1, 0.f);
                v2 = fmaxf(v2, 0.f); v3 = fmaxf(v3, 0.f);
            }
            *reinterpret_cast<float2*>(C + (size_t)gr * Nout + gc)       = make_float2(v0, v1);
            *reinterpret_cast<float2*>(C + (size_t)(gr + 8) * Nout + gc) = make_float2(v2, v3);
        }
    }
}

// ================= fused eproj GEMM + attention ====================
// grid = (2 heads, EE/128). Block tile = 128 edges x 128 cols (one full head).
// eproj stays in registers; epilogue does logits, softmax-exp, denom, scatter.
__global__ __launch_bounds__(256) void gemm_attn(
    const float* __restrict__ Amsg, const float* __restrict__ Ate,
    const float* __restrict__ We, const int* __restrict__ edge_idx)
{
    __shared__ unsigned As[2][TBM][KPAD];
    __shared__ unsigned Ws[2][TBN][KPAD];
    __shared__ int   sSrc[128];
    __shared__ int   sDst[128];
    __shared__ float sPart[4][128];
    __shared__ float sX[128];

    const int t    = threadIdx.x;
    const int warp = t >> 5;
    const int lane = t & 31;
    const int g    = lane >> 2;
    const int tig  = lane & 3;
    const int wm   = warp >> 2;
    const int wn   = warp & 3;
    const int h    = blockIdx.x;          // head
    const int row0 = blockIdx.y * TBM;    // edge base
    const int col0 = h * 128;             // We row base
    const int K    = EDGED;

    if (t < 128) {
        sSrc[t] = edge_idx[row0 + t];
        sDst[t] = edge_idx[EE + row0 + t];
    }

    float acc[4][4][4];
    #pragma unroll
    for (int i = 0; i < 4; i++)
        #pragma unroll
        for (int j = 0; j < 4; j++)
            #pragma unroll
            for (int c = 0; c < 4; c++) acc[i][j][c] = 0.f;

    auto ldA = [&](int idx, int k0) -> float4 {
        int r  = idx >> 2;
        int kb = k0 + (idx & 3) * 4;
        if (kb >= K) return make_float4(0.f, 0.f, 0.f, 0.f);
        int gr = row0 + r;
        return (kb < MSGD)
            ? *(const float4*)(Amsg + (size_t)gr * MSGD + kb)
            : *(const float4*)(Ate  + (size_t)gr * TDD  + (kb - MSGD));
    };
    auto ldW = [&](int idx, int k0) -> float4 {
        int n  = idx >> 2;
        int kb = k0 + (idx & 3) * 4;
        if (kb >= K) return make_float4(0.f, 0.f, 0.f, 0.f);
        return *(const float4*)(We + (size_t)(col0 + n) * K + kb);
    };
    auto store = [&](int buf, const float4* ra, const float4* rw) {
        #pragma unroll
        for (int i = 0; i < 2; i++) {
            int idx = t + i * 256;
            int r = idx >> 2, c4 = (idx & 3) * 4;
            As[buf][r][c4 + 0] = f2tf32(ra[i].x);
            As[buf][r][c4 + 1] = f2tf32(ra[i].y);
            As[buf][r][c4 + 2] = f2tf32(ra[i].z);
            As[buf][r][c4 + 3] = f2tf32(ra[i].w);
            Ws[buf][r][c4 + 0] = f2tf32(rw[i].x);
            Ws[buf][r][c4 + 1] = f2tf32(rw[i].y);
            Ws[buf][r][c4 + 2] = f2tf32(rw[i].z);
            Ws[buf][r][c4 + 3] = f2tf32(rw[i].w);
        }
    };
    auto compute = [&](int buf) {
        #pragma unroll
        for (int ks = 0; ks < TBK; ks += 8) {
            unsigned af[4][4], bf[4][2];
            #pragma unroll
            for (int mt = 0; mt < 4; mt++) {
                int rb = wm * 64 + mt * 16;
                af[mt][0] = As[buf][rb + g    ][ks + tig];
                af[mt][1] = As[buf][rb + g + 8][ks + tig];
                af[mt][2] = As[buf][rb + g    ][ks + tig + 4];
                af[mt][3] = As[buf][rb + g + 8][ks + tig + 4];
            }
            #pragma unroll
            for (int nt = 0; nt < 4; nt++) {
                int nb = wn * 32 + nt * 8;
                bf[nt][0] = Ws[buf][nb + g][ks + tig];
                bf[nt][1] = Ws[buf][nb + g][ks + tig + 4];
            }
            #pragma unroll
            for (int mt = 0; mt < 4; mt++)
                #pragma unroll
                for (int nt = 0; nt < 4; nt++)
                    MMA_TF32(acc[mt][nt], af[mt], bf[nt]);
        }
    };

    float4 ra[2], rw[2];
    #pragma unroll
    for (int i = 0; i < 2; i++) { ra[i] = ldA(t + i * 256, 0); rw[i] = ldW(t + i * 256, 0); }
    store(0, ra, rw);
    __syncthreads();
    int cur = 0;
    for (int k0 = TBK; k0 < K; k0 += TBK) {
        #pragma unroll
        for (int i = 0; i < 2; i++) { ra[i] = ldA(t + i * 256, k0); rw[i] = ldW(t + i * 256, k0); }
        compute(cur);
        store(cur ^ 1, ra, rw);
        __syncthreads();
        cur ^= 1;
    }
    compute(cur);

    // ---- epilogue: per-edge logits q.(k+ep) over this head's 128 cols ----
    const int hoff = h * 128;
    float part[4][2];
    #pragma unroll
    for (int mt = 0; mt < 4; mt++) { part[mt][0] = 0.f; part[mt][1] = 0.f; }

    #pragma unroll
    for (int mt = 0; mt < 4; mt++) {
        int r1 = wm * 64 + mt * 16 + g;
        int r2 = r1 + 8;
        int d1 = sDst[r1], s1 = sSrc[r1];
        int d2 = sDst[r2], s2 = sSrc[r2];
        #pragma unroll
        for (int nt = 0; nt < 4; nt++) {
            int cl = hoff + wn * 32 + nt * 8 + tig * 2;
            float2 q1 = *(const float2*)(g_qkvs + (size_t)d1 * 1024 + cl);
            float2 k1 = *(const float2*)(g_qkvs + (size_t)s1 * 1024 + 256 + cl);
            float2 q2 = *(const float2*)(g_qkvs + (size_t)d2 * 1024 + cl);
            float2 k2 = *(const float2*)(g_qkvs + (size_t)s2 * 1024 + 256 + cl);
            part[mt][0] += q1.x * (k1.x + acc[mt][nt][0]) + q1.y * (k1.y + acc[mt][nt][1]);
            part[mt][1] += q2.x * (k2.x + acc[mt][nt][2]) + q2.y * (k2.y + acc[mt][nt][3]);
        }
    }
    // reduce over tig (4 adjacent lanes)
    #pragma unroll
    for (int mt = 0; mt < 4; mt++) {
        #pragma unroll
        for (int half = 0; half < 2; half++) {
            float p = part[mt][half];
            p += __shfl_xor_sync(0xffffffffu, p, 1);
            p += __shfl_xor_sync(0xffffffffu, p, 2);
            part[mt][half] = p;
        }
    }
    if (tig == 0) {
        #pragma unroll
        for (int mt = 0; mt < 4; mt++) {
            sPart[wn][wm * 64 + mt * 16 + g]     = part[mt][0];
            sPart[wn][wm * 64 + mt * 16 + g + 8] = part[mt][1];
        }
    }
    __syncthreads();

    if (t < 128) {
        const float scal = 0.08838834764831845f;   // 1/sqrt(128)
        float a = sPart[0][t] + sPart[1][t] + sPart[2][t] + sPart[3][t];
        float x = expf(a * scal);
        sX[t] = x;
        atomicAdd(&g_denom[2 * sDst[t] + h], x);
    }
    __syncthreads();

    // ---- scatter (v + ep) * x ----
    #pragma unroll
    for (int mt = 0; mt < 4; mt++) {
        int r1 = wm * 64 + mt * 16 + g;
        int r2 = r1 + 8;
        int d1 = sDst[r1], s1 = sSrc[r1];
        int d2 = sDst[r2], s2 = sSrc[r2];
        float x1 = sX[r1], x2 = sX[r2];
        #pragma unroll
        for (int nt = 0; nt < 4; nt++) {
            int cl = hoff + wn * 32 + nt * 8 + tig * 2;
            float2 v1 = *(const float2*)(g_qkvs + (size_t)s1 * 1024 + 512 + cl);
            float2 v2 = *(const float2*)(g_qkvs + (size_t)s2 * 1024 + 512 + cl);
            float* a1 = g_agg + (size_t)d1 * 256 + cl;
            float* a2 = g_agg + (size_t)d2 * 256 + cl;
            atomicAdd(a1,     (v1.x + acc[mt][nt][0]) * x1);
            atomicAdd(a1 + 1, (v1.y + acc[mt][nt][1]) * x1);
            atomicAdd(a2,     (v2.x + acc[mt][nt][2]) * x2);
            atomicAdd(a2 + 1, (v2.y + acc[mt][nt][3]) * x2);
        }
    }
}

// ---------------- zero atomic accumulators ----------------
__global__ void k_zero()
{
    int i = blockIdx.x * blockDim.x + threadIdx.x;
    float4 z = make_float4(0.f, 0.f, 0.f, 0.f);
    if (i < NN * 64) ((float4*)g_agg)[i] = z;
    if (i < NN / 2)  ((float4*)g_denom)[i] = z;
}

// ---------------- build GRU input (warp per node) ----------------
__global__ __launch_bounds__(256) void k_build_aggr(
    const int* __restrict__ node_ids, const int* __restrict__ mem_last_update,
    const int* __restrict__ mem_rel_t, const int* __restrict__ mem_dst_id,
    const float* __restrict__ mem_table, const float* __restrict__ mem_msg_table,
    const float* __restrict__ mem_dir,
    const float* __restrict__ te_w, const float* __restrict__ te_b)
{
    const int lane = threadIdx.x & 31;
    const int nwarps = gridDim.x * 8;
    const float4 w4 = ((const float4*)te_w)[lane];
    const float4 b4 = ((const float4*)te_b)[lane];
    for (int n = blockIdx.x * 8 + (threadIdx.x >> 5); n < NN; n += nwarps) {
        const int nid = node_ids[n];
        const int did = mem_dst_id[nid];
        const float d0 = mem_dir[2 * nid], d1 = mem_dir[2 * nid + 1];
        const float4* sm4 = (const float4*)(mem_table + (size_t)nid * MEMD);
        const float4* dm4 = (const float4*)(mem_table + (size_t)did * MEMD);
        float4* ag = (float4*)(g_aggr + (size_t)n * GRUIN);
        float4* hh = (float4*)(g_h + (size_t)n * MEMD);
        #pragma unroll
        for (int i = 0; i < 2; i++) {
            int j = lane + i * 32;
            float4 s = sm4[j], d = dm4[j];
            ag[j]      = make_float4(s.x*d0 + d.x*d1, s.y*d0 + d.y*d1,
                                     s.z*d0 + d.z*d1, s.w*d0 + d.w*d1);
            ag[64 + j] = make_float4(s.x*d1 + d.x*d0, s.y*d1 + d.y*d0,
                                     s.z*d1 + d.z*d0, s.w*d1 + d.w*d0);
            hh[j] = s;
        }
        const float4* mg = (const float4*)(mem_msg_table + (size_t)nid * MSGD);
        for (int j = lane; j < MSGD / 4; j += 32) ag[128 + j] = mg[j];
        float rt = (float)mem_rel_t[nid];
        ag[171 + lane] = make_float4(cosf(rt * w4.x + b4.x), cosf(rt * w4.y + b4.y),
                                     cosf(rt * w4.z + b4.z), cosf(rt * w4.w + b4.w));
        if (lane == 0) g_lu[n] = (float)mem_last_update[nid];
    }
}

// ---------------- GRU gate combine ----------------
__global__ void k_gru()
{
    int i4 = blockIdx.x * blockDim.x + threadIdx.x;
    if (i4 >= NN * 64) return;
    int n = i4 >> 6, c4 = (i4 & 63) * 4;
    const float* gi = g_gi + (size_t)n * G3;
    const float* gh = g_gh + (size_t)n * G3;
    float4 ir = *(const float4*)(gi + c4);
    float4 iz = *(const float4*)(gi + 256 + c4);
    float4 in_ = *(const float4*)(gi + 512 + c4);
    float4 hr = *(const float4*)(gh + c4);
    float4 hz = *(const float4*)(gh + 256 + c4);
    float4 hn = *(const float4*)(gh + 512 + c4);
    float4 hv = *(const float4*)(g_h + (size_t)n * MEMD + c4);
    float4 o;
    {
        float r = 1.f/(1.f+expf(-(ir.x+hr.x))), z = 1.f/(1.f+expf(-(iz.x+hz.x)));
        o.x = (1.f-z)*tanhf(in_.x + r*hn.x) + z*hv.x;
    }{
        float r = 1.f/(1.f+expf(-(ir.y+hr.y))), z = 1.f/(1.f+expf(-(iz.y+hz.y)));
        o.y = (1.f-z)*tanhf(in_.y + r*hn.y) + z*hv.y;
    }{
        float r = 1.f/(1.f+expf(-(ir.z+hr.z))), z = 1.f/(1.f+expf(-(iz.z+hz.z)));
        o.z = (1.f-z)*tanhf(in_.z + r*hn.z) + z*hv.z;
    }{
        float r = 1.f/(1.f+expf(-(ir.w+hr.w))), z = 1.f/(1.f+expf(-(iz.w+hz.w)));
        o.w = (1.f-z)*tanhf(in_.w + r*hn.w) + z*hv.w;
    }
    *(float4*)(g_mem + (size_t)n * MEMD + c4) = o;
}

// ---------------- edge time-encoding ----------------
__global__ __launch_bounds__(256) void k_build_te(
    const int* __restrict__ edge_idx, const float* __restrict__ edge_t,
    const float* __restrict__ te_w, const float* __restrict__ te_b)
{
    const int lane = threadIdx.x & 31;
    const int nwarps = gridDim.x * 8;
    const float4 w4 = ((const float4*)te_w)[lane];
    const float4 b4 = ((const float4*)te_b)[lane];
    for (int e = blockIdx.x * 8 + (threadIdx.x >> 5); e < EE; e += nwarps) {
        float rel = g_lu[edge_idx[e]] - edge_t[e];
        ((float4*)(g_te + (size_t)e * TDD))[lane] =
            make_float4(cosf(rel * w4.x + b4.x), cosf(rel * w4.y + b4.y),
                        cosf(rel * w4.z + b4.z), cosf(rel * w4.w + b4.w));
    }
}

// ---------------- z = skip + agg/denom ----------------
__global__ void k_zfin()
{
    int i4 = blockIdx.x * blockDim.x + threadIdx.x;
    if (i4 >= NN * 64) return;
    int n = i4 >> 6, c4 = (i4 & 63) * 4;
    float rinv = 1.f / (g_denom[2 * n + (c4 >> 7)] + 1e-16f);
    float4 a  = *(const float4*)(g_agg + (size_t)n * 256 + c4);
    float4 sk = *(const float4*)(g_qkvs + (size_t)n * 1024 + 768 + c4);
    *(float4*)(g_z + (size_t)n * 256 + c4) =
        make_float4(sk.x + a.x * rinv, sk.y + a.y * rinv,
                    sk.z + a.z * rinv, sk.w + a.w * rinv);
}

// ---------------- final dot + mask + sigmoid ----------------
__global__ __launch_bounds__(256) void k_final(
    const int* __restrict__ node_idx, const float* __restrict__ lp_fw,
    const float* __restrict__ lp_fb, float* __restrict__ out)
{
    const int r = blockIdx.x * 8 + (threadIdx.x >> 5);
    const int lane = threadIdx.x & 31;
    if (r >= 2 * BB) return;
    const float4* h4 = (const float4*)(g_hid + (size_t)r * 256);
    const float4* w4 = (const float4*)lp_fw;
    float4 a = h4[lane], b = w4[lane];
    float4 a2 = h4[32 + lane], b2 = w4[32 + lane];
    float s = a.x*b.x + a.y*b.y + a.z*b.z + a.w*b.w
            + a2.x*b2.x + a2.y*b2.y + a2.z*b2.z + a2.w*b2.w;
    #pragma unroll
    for (int o = 16; o; o >>= 1) s += __shfl_xor_sync(0xffffffffu, s, o);
    if (lane == 0) {
        int bidx = r & (BB - 1);
        float mask = (node_idx[bidx] < NN - 1) ? 1.f : 0.f;
        float val = (s + lp_fb[0]) * mask;
        out[r] = 1.f / (1.f + expf(-val));
    }
}

// ---------------- launch ----------------
extern "C" void kernel_launch(void* const* d_in, const int* in_sizes, int n_in,
                              void* d_out, int out_size)
{
    const int*   node_ids        = (const int*)  d_in[0];
    const int*   node_idx        = (const int*)  d_in[1];
    const int*   edge_idx        = (const int*)  d_in[2];
    const int*   mem_last_update = (const int*)  d_in[3];
    const int*   mem_rel_t       = (const int*)  d_in[4];
    const int*   mem_dst_id      = (const int*)  d_in[5];
    const float* edge_t          = (const float*)d_in[6];
    const float* edge_msg        = (const float*)d_in[7];
    const float* mem_table       = (const float*)d_in[8];
    const float* mem_msg_table   = (const float*)d_in[9];
    const float* mem_dir         = (const float*)d_in[10];
    const float* te_mem_w        = (const float*)d_in[11];
    const float* te_mem_b        = (const float*)d_in[12];
    const float* gru_w_ih        = (const float*)d_in[13];
    const float* gru_w_hh        = (const float*)d_in[14];
    const float* gru_b_ih        = (const float*)d_in[15];
    const float* gru_b_hh        = (const float*)d_in[16];
    const float* te_gnn_w        = (const float*)d_in[17];
    const float* te_gnn_b        = (const float*)d_in[18];
    const float* Wq              = (const float*)d_in[19];
    const float* bq              = (const float*)d_in[20];
    const float* Wk              = (const float*)d_in[21];
    const float* bk              = (const float*)d_in[22];
    const float* Wv              = (const float*)d_in[23];
    const float* bv              = (const float*)d_in[24];
    const float* We              = (const float*)d_in[25];
    const float* Wskip           = (const float*)d_in[26];
    const float* bskip           = (const float*)d_in[27];
    const float* lp_hw           = (const float*)d_in[28];
    const float* lp_hb           = (const float*)d_in[29];
    const float* lp_fw           = (const float*)d_in[30];
    const float* lp_fb           = (const float*)d_in[31];

    float *p_aggr, *p_h, *p_gi, *p_gh, *p_mem, *p_qkvs, *p_te, *p_z, *p_hid;
    cudaGetSymbolAddress((void**)&p_aggr, g_aggr);
    cudaGetSymbolAddress((void**)&p_h,    g_h);
    cudaGetSymbolAddress((void**)&p_gi,   g_gi);
    cudaGetSymbolAddress((void**)&p_gh,   g_gh);
    cudaGetSymbolAddress((void**)&p_mem,  g_mem);
    cudaGetSymbolAddress((void**)&p_qkvs, g_qkvs);
    cudaGetSymbolAddress((void**)&p_te,   g_te);
    cudaGetSymbolAddress((void**)&p_z,    g_z);
    cudaGetSymbolAddress((void**)&p_hid,  g_hid);

    k_zero<<<4096, 256>>>();

    // ---- memory (GRU) ----
    k_build_aggr<<<2048, 256>>>(node_ids, mem_last_update, mem_rel_t, mem_dst_id,
                                mem_table, mem_msg_table, mem_dir, te_mem_w, te_mem_b);
    gemm3<0><<<dim3(G3 / TBN, NN / TBM), 256>>>(
        p_aggr, nullptr,
        gru_w_ih, nullptr, nullptr, nullptr,
        gru_b_ih, nullptr, nullptr, nullptr,
        p_gi, G3, GRUIN, 0);
    gemm3<0><<<dim3(G3 / TBN, NN / TBM), 256>>>(
        p_h, nullptr,
        gru_w_hh, nullptr, nullptr, nullptr,
        gru_b_hh, nullptr, nullptr, nullptr,
        p_gh, G3, MEMD, 0);
    k_gru<<<4096, 256>>>();

    // ---- fused q|k|v|skip projection ----
    gemm3<3><<<dim3(1024 / TBN, NN / TBM), 256>>>(
        p_mem, nullptr,
        Wq, Wk, Wv, Wskip,
        bq, bk, bv, bskip,
        p_qkvs, 1024, MEMD, 0);

    // ---- fused edge projection + attention + scatter ----
    k_build_te<<<2048, 256>>>(edge_idx, edge_t, te_gnn_w, te_gnn_b);
    gemm_attn<<<dim3(2, EE / TBM), 256>>>(edge_msg, p_te, We, edge_idx);

    k_zfin<<<4096, 256>>>();

    // ---- link predictor ----
    gemm3<2><<<dim3(MEMD / TBN, (2 * BB) / TBM), 256>>>(
        p_z, node_idx,
        lp_hw, nullptr, nullptr, nullptr,
        lp_hb, nullptr, nullptr, nullptr,
        p_hid, MEMD, 2 * MEMD, 1);
    k_final<<<1024, 256>>>(node_idx, lp_fw, lp_fb, (float*)d_out);
}

// round 5
// speedup vs baseline: 3.3555x; 1.1449x over previous
#include <cuda_runtime.h>
#include <math.h>
#include <stdint.h>

// ---------------- problem constants ----------------
#define NN     16384
#define BB     4096
#define EE     131072
#define MEMD   256
#define TDD    128
#define MSGD   172
#define EDGED  300
#define GRUIN  812
#define G3     768

// ---------------- device scratch ----------------
__device__ float g_aggr [(size_t)NN * GRUIN];
__device__ float g_h    [(size_t)NN * MEMD];
__device__ float g_lu   [NN];
__device__ float g_gi   [(size_t)NN * G3];
__device__ float g_gh   [(size_t)NN * G3];
__device__ float g_mem  [(size_t)NN * MEMD];
__device__ float g_qkvs [(size_t)NN * 1024];   // [q | k | v | skip]
__device__ float g_denom[(size_t)NN * 2];
__device__ float g_agg  [(size_t)NN * MEMD];
__device__ float g_z    [(size_t)NN * MEMD];
__device__ float g_hid  [(size_t)2 * BB * 256];

#define TBM 128
#define TBN 128
#define TBK 16
#define KPAD 20
#define STG 3
#define SMEM_BYTES (2 * STG * TBM * KPAD * 4)   // 61440

#define MMA_TF32(acc, af, bf)                                              \
    asm volatile(                                                          \
        "mma.sync.aligned.m16n8k8.row.col.f32.tf32.tf32.f32 "              \
        "{%0,%1,%2,%3}, {%4,%5,%6,%7}, {%8,%9}, {%0,%1,%2,%3};"            \
        : "+f"(acc[0]), "+f"(acc[1]), "+f"(acc[2]), "+f"(acc[3])           \
        : "r"(af[0]), "r"(af[1]), "r"(af[2]), "r"(af[3]),                  \
          "r"(bf[0]), "r"(bf[1]))

__device__ __forceinline__ void cp16(uint32_t dst, const void* src) {
    asm volatile("cp.async.cg.shared.global [%0], [%1], 16;"
                 :: "r"(dst), "l"(src));
}
__device__ __forceinline__ void cp16z(uint32_t dst, const void* src, bool pred) {
    int sz = pred ? 16 : 0;
    asm volatile("cp.async.cg.shared.global [%0], [%1], 16, %2;"
                 :: "r"(dst), "l"(src), "r"(sz));
}
#define CP_COMMIT asm volatile("cp.async.commit_group;")
#define CP_WAIT1  asm volatile("cp.async.wait_group 1;")

// ================= generic cp.async tf32 GEMM (modes 0/2/3) =================
// C[M,Nout] = A[M,K] @ W[Nout,K]^T + bias. 3-stage cp.async, raw f32 -> tf32.
template<int MODE>
__global__ __launch_bounds__(256) void gemm4(
    const float* __restrict__ A, const int* __restrict__ gidx,
    const float* __restrict__ W0c, const float* __restrict__ W1c,
    const float* __restrict__ W2c, const float* __restrict__ W3c,
    const float* __restrict__ b0c, const float* __restrict__ b1c,
    const float* __restrict__ b2c, const float* __restrict__ b3c,
    float* __restrict__ C, int Nout, int K, int do_relu)
{
    extern __shared__ unsigned dynsmem[];
    unsigned (*As)[TBM][KPAD] = reinterpret_cast<unsigned(*)[TBM][KPAD]>(dynsmem);
    unsigned (*Ws)[TBN][KPAD] = reinterpret_cast<unsigned(*)[TBN][KPAD]>(dynsmem + STG * TBM * KPAD);
    const uint32_t sb_a = (uint32_t)__cvta_generic_to_shared(dynsmem);
    const uint32_t sb_w = sb_a + STG * TBM * KPAD * 4;

    const int t    = threadIdx.x;
    const int warp = t >> 5;
    const int lane = t & 31;
    const int g    = lane >> 2;
    const int tig  = lane & 3;
    const int wm   = warp >> 2;
    const int wn   = warp & 3;
    const int row0 = blockIdx.y * TBM;
    const int col0 = blockIdx.x * TBN;

    const float* Wsel = W0c;
    const float* bsel = b0c;
    int colL = col0;
    if (MODE == 3) {
        int grp = col0 >> 8;
        Wsel = (grp == 0) ? W0c : (grp == 1) ? W1c : (grp == 2) ? W2c : W3c;
        bsel = (grp == 0) ? b0c : (grp == 1) ? b1c : (grp == 2) ? b2c : b3c;
        colL = col0 & 255;
    }

    float acc[4][4][4];
    #pragma unroll
    for (int i = 0; i < 4; i++)
        #pragma unroll
        for (int j = 0; j < 4; j++)
            #pragma unroll
            for (int c = 0; c < 4; c++) acc[i][j][c] = 0.f;

    auto issue = [&](int s, int k0) {
        #pragma unroll
        for (int i = 0; i < 2; i++) {
            int idx = t + i * 256;
            int r = idx >> 2, c4 = (idx & 3) * 4;
            int kb = k0 + c4;
            bool ok = kb < K;
            int kc = ok ? kb : 0;
            // A chunk
            const float* srcA;
            if (MODE == 2) {
                int gr = row0 + r;
                int b = gr & (BB - 1), side = gr >> 12;
                int kk  = (kc < 256) ? kc : kc - 256;
                int ii  = (kc < 256) ? gidx[b] : gidx[BB + side * BB + b];
                srcA = A + (size_t)ii * 256 + kk;
            } else {
                srcA = A + (size_t)(row0 + r) * K + kc;
            }
            cp16z(sb_a + (uint32_t)(((s * TBM + r) * KPAD + c4) * 4), srcA, ok);
            // W chunk
            cp16z(sb_w + (uint32_t)(((s * TBN + r) * KPAD + c4) * 4),
                  Wsel + (size_t)(colL + r) * K + kc, ok);
        }
    };
    auto compute = [&](int buf) {
        #pragma unroll
        for (int ks = 0; ks < TBK; ks += 8) {
            unsigned af[4][4], bf[4][2];
            #pragma unroll
            for (int mt = 0; mt < 4; mt++) {
                int rb = wm * 64 + mt * 16;
                af[mt][0] = As[buf][rb + g    ][ks + tig];
                af[mt][1] = As[buf][rb + g + 8][ks + tig];
                af[mt][2] = As[buf][rb + g    ][ks + tig + 4];
                af[mt][3] = As[buf][rb + g + 8][ks + tig + 4];
            }
            #pragma unroll
            for (int nt = 0; nt < 4; nt++) {
                int nb = wn * 32 + nt * 8;
                bf[nt][0] = Ws[buf][nb + g][ks + tig];
                bf[nt][1] = Ws[buf][nb + g][ks + tig + 4];
            }
            #pragma unroll
            for (int mt = 0; mt < 4; mt++)
                #pragma unroll
                for (int nt = 0; nt < 4; nt++)
                    MMA_TF32(acc[mt][nt], af[mt], bf[nt]);
        }
    };

    const int ktiles = (K + TBK - 1) / TBK;
    issue(0, 0);        CP_COMMIT;
    issue(1, TBK);      CP_COMMIT;
    int fetch = 2;
    for (int j = 0; j < ktiles; j++) {
        CP_WAIT1;
        __syncthreads();
        compute(j % STG);
        if (fetch < ktiles) { issue(fetch % STG, fetch * TBK); fetch++; }
        CP_COMMIT;
    }

    #pragma unroll
    for (int mt = 0; mt < 4; mt++) {
        int gr = row0 + wm * 64 + mt * 16 + g;
        #pragma unroll
        for (int nt = 0; nt < 4; nt++) {
            int nl = colL + wn * 32 + nt * 8 + tig * 2;
            int gc = col0 + wn * 32 + nt * 8 + tig * 2;
            float bb0 = bsel ? bsel[nl]     : 0.f;
            float bb1 = bsel ? bsel[nl + 1] : 0.f;
            float v0 = acc[mt][nt][0] + bb0;
            float v1 = acc[mt][nt][1] + bb1;
            float v2 = acc[mt][nt][2] + bb0;
            float v3 = acc[mt][nt][3] + bb1;
            if (do_relu) {
                v0 = fmaxf(v0, 0.f); v1 = fmaxf(v1, 0.f);
                v2 = fmaxf(v2, 0.f); v3 = fmaxf(v3, 0.f);
            }
            *reinterpret_cast<float2*>(C + (size_t)gr * Nout + gc)       = make_float2(v0, v1);
            *reinterpret_cast<float2*>(C + (size_t)(gr + 8) * Nout + gc) = make_float2(v2, v3);
        }
    }
}

// ========== fused edge GEMM + time-enc + attention + scatter ==========
// grid = (2 heads, EE/128). A = [edge_msg | cos(time-enc)] computed in-stage.
__global__ __launch_bounds__(256) void gemm_attn(
    const float* __restrict__ Amsg, const int* __restrict__ edge_idx,
    const float* __restrict__ edge_t,
    const float* __restrict__ te_w, const float* __restrict__ te_b,
    const float* __restrict__ We)
{
    extern __shared__ unsigned dynsmem[];
    unsigned (*As)[TBM][KPAD] = reinterpret_cast<unsigned(*)[TBM][KPAD]>(dynsmem);
    unsigned (*Ws)[TBN][KPAD] = reinterpret_cast<unsigned(*)[TBN][KPAD]>(dynsmem + STG * TBM * KPAD);
    const uint32_t sb_a = (uint32_t)__cvta_generic_to_shared(dynsmem);
    const uint32_t sb_w = sb_a + STG * TBM * KPAD * 4;

    __shared__ int   sSrc[128];
    __shared__ int   sDst[128];
    __shared__ float sPart[4][128];
    __shared__ float sX[128];

    const int t    = threadIdx.x;
    const int warp = t >> 5;
    const int lane = t & 31;
    const int g    = lane >> 2;
    const int tig  = lane & 3;
    const int wm   = warp >> 2;
    const int wn   = warp & 3;
    const int h    = blockIdx.x;
    const int row0 = blockIdx.y * TBM;
    const int col0 = h * 128;
    const int K    = EDGED;

    if (t < 128) {
        sSrc[t] = edge_idx[row0 + t];
        sDst[t] = edge_idx[EE + row0 + t];
    }

    float acc[4][4][4];
    #pragma unroll
    for (int i = 0; i < 4; i++)
        #pragma unroll
        for (int j = 0; j < 4; j++)
            #pragma unroll
            for (int c = 0; c < 4; c++) acc[i][j][c] = 0.f;

    auto issue = [&](int s, int k0) {
        #pragma unroll
        for (int i = 0; i < 2; i++) {
            int idx = t + i * 256;
            int r = idx >> 2, c4 = (idx & 3) * 4;
            int kb = k0 + c4;
            int gr = row0 + r;
            unsigned* ap = &As[s][r][c4];
            if (kb < MSGD) {           // pure msg chunk (boundary is chunk-aligned: 168+4=172)
                cp16(sb_a + (uint32_t)(((s * TBM + r) * KPAD + c4) * 4),
                     Amsg + (size_t)gr * MSGD + kb);
            } else if (kb < EDGED) {   // time-encoding chunk
                int src = edge_idx[gr];
                float rel = g_lu[src] - edge_t[gr];
                int c = kb - MSGD;
                ap[0] = __float_as_uint(cosf(rel * te_w[c + 0] + te_b[c + 0]));
                ap[1] = __float_as_uint(cosf(rel * te_w[c + 1] + te_b[c + 1]));
                ap[2] = __float_as_uint(cosf(rel * te_w[c + 2] + te_b[c + 2]));
                ap[3] = __float_as_uint(cosf(rel * te_w[c + 3] + te_b[c + 3]));
            } else {
                ap[0] = 0u; ap[1] = 0u; ap[2] = 0u; ap[3] = 0u;
            }
            bool ok = kb < K;
            cp16z(sb_w + (uint32_t)(((s * TBN + r) * KPAD + c4) * 4),
                  We + (size_t)(col0 + r) * K + (ok ? kb : 0), ok);
        }
    };
    auto compute = [&](int buf) {
        #pragma unroll
        for (int ks = 0; ks < TBK; ks += 8) {
            unsigned af[4][4], bf[4][2];
            #pragma unroll
            for (int mt = 0; mt < 4; mt++) {
                int rb = wm * 64 + mt * 16;
                af[mt][0] = As[buf][rb + g    ][ks + tig];
                af[mt][1] = As[buf][rb + g + 8][ks + tig];
                af[mt][2] = As[buf][rb + g    ][ks + tig + 4];
                af[mt][3] = As[buf][rb + g + 8][ks + tig + 4];
            }
            #pragma unroll
            for (int nt = 0; nt < 4; nt++) {
                int nb = wn * 32 + nt * 8;
                bf[nt][0] = Ws[buf][nb + g][ks + tig];
                bf[nt][1] = Ws[buf][nb + g][ks + tig + 4];
            }
            #pragma unroll
            for (int mt = 0; mt < 4; mt++)
                #pragma unroll
                for (int nt = 0; nt < 4; nt++)
                    MMA_TF32(acc[mt][nt], af[mt], bf[nt]);
        }
    };

    const int ktiles = (K + TBK - 1) / TBK;   // 19
    issue(0, 0);   CP_COMMIT;
    issue(1, TBK); CP_COMMIT;
    int fetch = 2;
    for (int j = 0; j < ktiles; j++) {
        CP_WAIT1;
        __syncthreads();
        compute(j % STG);
        if (fetch < ktiles) { issue(fetch % STG, fetch * TBK); fetch++; }
        CP_COMMIT;
    }

    // ---- epilogue: logits q.(k+ep) ----
    const int hoff = h * 128;
    float part[4][2];
    #pragma unroll
    for (int mt = 0; mt < 4; mt++) { part[mt][0] = 0.f; part[mt][1] = 0.f; }

    #pragma unroll
    for (int mt = 0; mt < 4; mt++) {
        int r1 = wm * 64 + mt * 16 + g;
        int r2 = r1 + 8;
        int d1 = sDst[r1], s1 = sSrc[r1];
        int d2 = sDst[r2], s2 = sSrc[r2];
        #pragma unroll
        for (int nt = 0; nt < 4; nt++) {
            int cl = hoff + wn * 32 + nt * 8 + tig * 2;
            float2 q1 = *(const float2*)(g_qkvs + (size_t)d1 * 1024 + cl);
            float2 k1 = *(const float2*)(g_qkvs + (size_t)s1 * 1024 + 256 + cl);
            float2 q2 = *(const float2*)(g_qkvs + (size_t)d2 * 1024 + cl);
            float2 k2 = *(const float2*)(g_qkvs + (size_t)s2 * 1024 + 256 + cl);
            part[mt][0] += q1.x * (k1.x + acc[mt][nt][0]) + q1.y * (k1.y + acc[mt][nt][1]);
            part[mt][1] += q2.x * (k2.x + acc[mt][nt][2]) + q2.y * (k2.y + acc[mt][nt][3]);
        }
    }
    #pragma unroll
    for (int mt = 0; mt < 4; mt++) {
        #pragma unroll
        for (int half = 0; half < 2; half++) {
            float p = part[mt][half];
            p += __shfl_xor_sync(0xffffffffu, p, 1);
            p += __shfl_xor_sync(0xffffffffu, p, 2);
            part[mt][half] = p;
        }
    }
    if (tig == 0) {
        #pragma unroll
        for (int mt = 0; mt < 4; mt++) {
            sPart[wn][wm * 64 + mt * 16 + g]     = part[mt][0];
            sPart[wn][wm * 64 + mt * 16 + g + 8] = part[mt][1];
        }
    }
    __syncthreads();

    if (t < 128) {
        const float scal = 0.08838834764831845f;   // 1/sqrt(128)
        float a = sPart[0][t] + sPart[1][t] + sPart[2][t] + sPart[3][t];
        float x = expf(a * scal);
        sX[t] = x;
        atomicAdd(&g_denom[2 * sDst[t] + h], x);
    }
    __syncthreads();

    // ---- scatter (v + ep) * x with vector atomics ----
    #pragma unroll
    for (int mt = 0; mt < 4; mt++) {
        int r1 = wm * 64 + mt * 16 + g;
        int r2 = r1 + 8;
        int d1 = sDst[r1], s1 = sSrc[r1];
        int d2 = sDst[r2], s2 = sSrc[r2];
        float x1 = sX[r1], x2 = sX[r2];
        #pragma unroll
        for (int nt = 0; nt < 4; nt++) {
            int cl = hoff + wn * 32 + nt * 8 + tig * 2;
            float2 v1 = *(const float2*)(g_qkvs + (size_t)s1 * 1024 + 512 + cl);
            float2 v2 = *(const float2*)(g_qkvs + (size_t)s2 * 1024 + 512 + cl);
            atomicAdd((float2*)(g_agg + (size_t)d1 * 256 + cl),
                      make_float2((v1.x + acc[mt][nt][0]) * x1,
                                  (v1.y + acc[mt][nt][1]) * x1));
            atomicAdd((float2*)(g_agg + (size_t)d2 * 256 + cl),
                      make_float2((v2.x + acc[mt][nt][2]) * x2,
                                  (v2.y + acc[mt][nt][3]) * x2));
        }
    }
}

// ---------------- zero atomic accumulators ----------------
__global__ void k_zero()
{
    int i = blockIdx.x * blockDim.x + threadIdx.x;
    float4 z = make_float4(0.f, 0.f, 0.f, 0.f);
    if (i < NN * 64) ((float4*)g_agg)[i] = z;
    if (i < NN / 2)  ((float4*)g_denom)[i] = z;
}

// ---------------- build GRU input (warp per node) ----------------
__global__ __launch_bounds__(256) void k_build_aggr(
    const int* __restrict__ node_ids, const int* __restrict__ mem_last_update,
    const int* __restrict__ mem_rel_t, const int* __restrict__ mem_dst_id,
    const float* __restrict__ mem_table, const float* __restrict__ mem_msg_table,
    const float* __restrict__ mem_dir,
    const float* __restrict__ te_w, const float* __restrict__ te_b)
{
    const int lane = threadIdx.x & 31;
    const int nwarps = gridDim.x * 8;
    const float4 w4 = ((const float4*)te_w)[lane];
    const float4 b4 = ((const float4*)te_b)[lane];
    for (int n = blockIdx.x * 8 + (threadIdx.x >> 5); n < NN; n += nwarps) {
        const int nid = node_ids[n];
        const int did = mem_dst_id[nid];
        const float d0 = mem_dir[2 * nid], d1 = mem_dir[2 * nid + 1];
        const float4* sm4 = (const float4*)(mem_table + (size_t)nid * MEMD);
        const float4* dm4 = (const float4*)(mem_table + (size_t)did * MEMD);
        float4* ag = (float4*)(g_aggr + (size_t)n * GRUIN);
        float4* hh = (float4*)(g_h + (size_t)n * MEMD);
        #pragma unroll
        for (int i = 0; i < 2; i++) {
            int j = lane + i * 32;
            float4 s = sm4[j], d = dm4[j];
            ag[j]      = make_float4(s.x*d0 + d.x*d1, s.y*d0 + d.y*d1,
                                     s.z*d0 + d.z*d1, s.w*d0 + d.w*d1);
            ag[64 + j] = make_float4(s.x*d1 + d.x*d0, s.y*d1 + d.y*d0,
                                     s.z*d1 + d.z*d0, s.w*d1 + d.w*d0);
            hh[j] = s;
        }
        const float4* mg = (const float4*)(mem_msg_table + (size_t)nid * MSGD);
        for (int j = lane; j < MSGD / 4; j += 32) ag[128 + j] = mg[j];
        float rt = (float)mem_rel_t[nid];
        ag[171 + lane] = make_float4(cosf(rt * w4.x + b4.x), cosf(rt * w4.y + b4.y),
                                     cosf(rt * w4.z + b4.z), cosf(rt * w4.w + b4.w));
        if (lane == 0) g_lu[n] = (float)mem_last_update[nid];
    }
}

// ---------------- GRU gate combine ----------------
__global__ void k_gru()
{
    int i4 = blockIdx.x * blockDim.x + threadIdx.x;
    if (i4 >= NN * 64) return;
    int n = i4 >> 6, c4 = (i4 & 63) * 4;
    const float* gi = g_gi + (size_t)n * G3;
    const float* gh = g_gh + (size_t)n * G3;
    float4 ir = *(const float4*)(gi + c4);
    float4 iz = *(const float4*)(gi + 256 + c4);
    float4 in_ = *(const float4*)(gi + 512 + c4);
    float4 hr = *(const float4*)(gh + c4);
    float4 hz = *(const float4*)(gh + 256 + c4);
    float4 hn = *(const float4*)(gh + 512 + c4);
    float4 hv = *(const float4*)(g_h + (size_t)n * MEMD + c4);
    float4 o;
    {
        float r = 1.f/(1.f+expf(-(ir.x+hr.x))), z = 1.f/(1.f+expf(-(iz.x+hz.x)));
        o.x = (1.f-z)*tanhf(in_.x + r*hn.x) + z*hv.x;
    }{
        float r = 1.f/(1.f+expf(-(ir.y+hr.y))), z = 1.f/(1.f+expf(-(iz.y+hz.y)));
        o.y = (1.f-z)*tanhf(in_.y + r*hn.y) + z*hv.y;
    }{
        float r = 1.f/(1.f+expf(-(ir.z+hr.z))), z = 1.f/(1.f+expf(-(iz.z+hz.z)));
        o.z = (1.f-z)*tanhf(in_.z + r*hn.z) + z*hv.z;
    }{
        float r = 1.f/(1.f+expf(-(ir.w+hr.w))), z = 1.f/(1.f+expf(-(iz.w+hz.w)));
        o.w = (1.f-z)*tanhf(in_.w + r*hn.w) + z*hv.w;
    }
    *(float4*)(g_mem + (size_t)n * MEMD + c4) = o;
}

// ---------------- z = skip + agg/denom ----------------
__global__ void k_zfin()
{
    int i4 = blockIdx.x * blockDim.x + threadIdx.x;
    if (i4 >= NN * 64) return;
    int n = i4 >> 6, c4 = (i4 & 63) * 4;
    float rinv = 1.f / (g_denom[2 * n + (c4 >> 7)] + 1e-16f);
    float4 a  = *(const float4*)(g_agg + (size_t)n * 256 + c4);
    float4 sk = *(const float4*)(g_qkvs + (size_t)n * 1024 + 768 + c4);
    *(float4*)(g_z + (size_t)n * 256 + c4) =
        make_float4(sk.x + a.x * rinv, sk.y + a.y * rinv,
                    sk.z + a.z * rinv, sk.w + a.w * rinv);
}

// ---------------- final dot + mask + sigmoid ----------------
__global__ __launch_bounds__(256) void k_final(
    const int* __restrict__ node_idx, const float* __restrict__ lp_fw,
    const float* __restrict__ lp_fb, float* __restrict__ out)
{
    const int r = blockIdx.x * 8 + (threadIdx.x >> 5);
    const int lane = threadIdx.x & 31;
    if (r >= 2 * BB) return;
    const float4* h4 = (const float4*)(g_hid + (size_t)r * 256);
    const float4* w4 = (const float4*)lp_fw;
    float4 a = h4[lane], b = w4[lane];
    float4 a2 = h4[32 + lane], b2 = w4[32 + lane];
    float s = a.x*b.x + a.y*b.y + a.z*b.z + a.w*b.w
            + a2.x*b2.x + a2.y*b2.y + a2.z*b2.z + a2.w*b2.w;
    #pragma unroll
    for (int o = 16; o; o >>= 1) s += __shfl_xor_sync(0xffffffffu, s, o);
    if (lane == 0) {
        int bidx = r & (BB - 1);
        float mask = (node_idx[bidx] < NN - 1) ? 1.f : 0.f;
        float val = (s + lp_fb[0]) * mask;
        out[r] = 1.f / (1.f + expf(-val));
    }
}

// ---------------- launch ----------------
extern "C" void kernel_launch(void* const* d_in, const int* in_sizes, int n_in,
                              void* d_out, int out_size)
{
    const int*   node_ids        = (const int*)  d_in[0];
    const int*   node_idx        = (const int*)  d_in[1];
    const int*   edge_idx        = (const int*)  d_in[2];
    const int*   mem_last_update = (const int*)  d_in[3];
    const int*   mem_rel_t       = (const int*)  d_in[4];
    const int*   mem_dst_id      = (const int*)  d_in[5];
    const float* edge_t          = (const float*)d_in[6];
    const float* edge_msg        = (const float*)d_in[7];
    const float* mem_table       = (const float*)d_in[8];
    const float* mem_msg_table   = (const float*)d_in[9];
    const float* mem_dir         = (const float*)d_in[10];
    const float* te_mem_w        = (const float*)d_in[11];
    const float* te_mem_b        = (const float*)d_in[12];
    const float* gru_w_ih        = (const float*)d_in[13];
    const float* gru_w_hh        = (const float*)d_in[14];
    const float* gru_b_ih        = (const float*)d_in[15];
    const float* gru_b_hh        = (const float*)d_in[16];
    const float* te_gnn_w        = (const float*)d_in[17];
    const float* te_gnn_b        = (const float*)d_in[18];
    const float* Wq              = (const float*)d_in[19];
    const float* bq              = (const float*)d_in[20];
    const float* Wk              = (const float*)d_in[21];
    const float* bk              = (const float*)d_in[22];
    const float* Wv              = (const float*)d_in[23];
    const float* bv              = (const float*)d_in[24];
    const float* We              = (const float*)d_in[25];
    const float* Wskip           = (const float*)d_in[26];
    const float* bskip           = (const float*)d_in[27];
    const float* lp_hw           = (const float*)d_in[28];
    const float* lp_hb           = (const float*)d_in[29];
    const float* lp_fw           = (const float*)d_in[30];
    const float* lp_fb           = (const float*)d_in[31];

    float *p_aggr, *p_h, *p_gi, *p_gh, *p_mem, *p_qkvs, *p_z, *p_hid;
    cudaGetSymbolAddress((void**)&p_aggr, g_aggr);
    cudaGetSymbolAddress((void**)&p_h,    g_h);
    cudaGetSymbolAddress((void**)&p_gi,   g_gi);
    cudaGetSymbolAddress((void**)&p_gh,   g_gh);
    cudaGetSymbolAddress((void**)&p_mem,  g_mem);
    cudaGetSymbolAddress((void**)&p_qkvs, g_qkvs);
    cudaGetSymbolAddress((void**)&p_z,    g_z);
    cudaGetSymbolAddress((void**)&p_hid,  g_hid);

    cudaFuncSetAttribute(gemm4<0>, cudaFuncAttributeMaxDynamicSharedMemorySize, SMEM_BYTES);
    cudaFuncSetAttribute(gemm4<2>, cudaFuncAttributeMaxDynamicSharedMemorySize, SMEM_BYTES);
    cudaFuncSetAttribute(gemm4<3>, cudaFuncAttributeMaxDynamicSharedMemorySize, SMEM_BYTES);
    cudaFuncSetAttribute(gemm_attn, cudaFuncAttributeMaxDynamicSharedMemorySize, SMEM_BYTES);

    k_zero<<<4096, 256>>>();

    // ---- memory (GRU) ----
    k_build_aggr<<<2048, 256>>>(node_ids, mem_last_update, mem_rel_t, mem_dst_id,
                                mem_table, mem_msg_table, mem_dir, te_mem_w, te_mem_b);
    gemm4<0><<<dim3(G3 / TBN, NN / TBM), 256, SMEM_BYTES>>>(
        p_aggr, nullptr,
        gru_w_ih, nullptr, nullptr, nullptr,
        gru_b_ih, nullptr, nullptr, nullptr,
        p_gi, G3, GRUIN, 0);
    gemm4<0><<<dim3(G3 / TBN, NN / TBM), 256, SMEM_BYTES>>>(
        p_h, nullptr,
        gru_w_hh, nullptr, nullptr, nullptr,
        gru_b_hh, nullptr, nullptr, nullptr,
        p_gh, G3, MEMD, 0);
    k_gru<<<4096, 256>>>();

    // ---- fused q|k|v|skip projection ----
    gemm4<3><<<dim3(1024 / TBN, NN / TBM), 256, SMEM_BYTES>>>(
        p_mem, nullptr,
        Wq, Wk, Wv, Wskip,
        bq, bk, bv, bskip,
        p_qkvs, 1024, MEMD, 0);

    // ---- fused edge projection + time-enc + attention + scatter ----
    gemm_attn<<<dim3(2, EE / TBM), 256, SMEM_BYTES>>>(
        edge_msg, edge_idx, edge_t, te_gnn_w, te_gnn_b, We);

    k_zfin<<<4096, 256>>>();

    // ---- link predictor ----
    gemm4<2><<<dim3(MEMD / TBN, (2 * BB) / TBM), 256, SMEM_BYTES>>>(
        p_z, node_idx,
        lp_hw, nullptr, nullptr, nullptr,
        lp_hb, nullptr, nullptr, nullptr,
        p_hid, MEMD, 2 * MEMD, 1);
    k_final<<<1024, 256>>>(node_idx, lp_fw, lp_fb, (float*)d_out);
}